// round 12
// baseline (speedup 1.0000x reference)
#include <cuda_runtime.h>
#include <cuda_fp16.h>
#include <mma.h>
#include <math.h>
#include <cstdint>

using namespace nvcuda;

#define NL   1200
#define NS   5
#define NPTS (NL*NS)      // 6000
#define DD   128
#define HH   128
#define WW   128
#define TK   10
#define GAPF 0.1f
#define NCAND_MAX 320
#define ERRB 0.0022f      // > 2 * fp16 dot error bound (2*9.8e-4)

#define LPB  25           // lines per tile side (25*5 = 125 rows of a 128 tile)
#define LDT  136          // smem leading dim, mult of 8

// ---------------- scratch (static __device__, no allocations) ----------------
static __device__ float g_d1[NPTS*DD];            // exact normalized descriptors
static __device__ float g_d2[NPTS*DD];
static __device__ __half g_h1[NPTS*DD];           // fp16 copies (same layout)
static __device__ __half g_h2[NPTS*DD];
static __device__ float g_t1[HH*WW*DD];           // desc transposed [y][x][d]
static __device__ float g_t2[HH*WW*DD];
static __device__ float g_ns[2][NL];
static __device__ float g_ls [NL*NL];             // APPROX line scores
static __device__ float g_lsT[NL*NL];
static __device__ int   g_topk[2][NL*TK];         // exact top-10, argsort order
static __device__ float g_nw [2][NL*2*TK];
static __device__ int   g_match[2][NL];

// Unfused helpers (match XLA's per-op rounding; no FMA contraction)
__device__ __forceinline__ float fm(float a, float b) { return __fmul_rn(a, b); }
__device__ __forceinline__ float fa(float a, float b) { return __fadd_rn(a, b); }
__device__ __forceinline__ float fs(float a, float b) { return __fsub_rn(a, b); }

// monotonic float<->uint for argsort-compatible keys
__device__ __forceinline__ unsigned enc_f(float v) {
    unsigned u = __float_as_uint(v);
    return (u & 0x80000000u) ? ~u : (u | 0x80000000u);
}
__device__ __forceinline__ float dec_f(unsigned u) {
    unsigned o = (u >> 31) ? (u & 0x7FFFFFFFu) : ~u;
    return __uint_as_float(o);
}

// ---------------- kernel 0: transpose desc [d][y][x] -> [y][x][d] ------------
__global__ void transpose_kernel(const float* __restrict__ desc1,
                                 const float* __restrict__ desc2) {
    __shared__ float tile[32][33];
    int z   = blockIdx.z;
    int set = z >> 7;                   // 0..1
    int y   = z & 127;
    const float* src = set ? desc2 : desc1;
    float*       dst = set ? g_t2  : g_t1;
    int d0 = blockIdx.y * 32;
    int x0 = blockIdx.x * 32;
    int tx = threadIdx.x, ty = threadIdx.y;   // 32 x 8
    #pragma unroll
    for (int i = 0; i < 32; i += 8)
        tile[ty+i][tx] = src[(d0+ty+i)*HH*WW + y*WW + x0+tx];
    __syncthreads();
    #pragma unroll
    for (int i = 0; i < 32; i += 8)
        dst[(y*WW + x0+ty+i)*DD + d0+tx] = tile[tx][ty+i];
}

// ---------------- kernel 1: sample points + bilinear descriptors -------------
// Gathers from the transposed layout: for a fixed corner, lane d reads
// consecutive floats -> fully coalesced. Arithmetic identical to before.
__global__ void sample_kernel(const float* __restrict__ seg1,
                              const float* __restrict__ seg2) {
    int warp = (blockIdx.x * blockDim.x + threadIdx.x) >> 5;
    int lane = threadIdx.x & 31;
    if (warp >= 2*NPTS) return;
    int set  = warp / NPTS;
    int p    = warp - set*NPTS;
    int line = p / NS;
    int k    = p - line*NS;

    const float* seg = set ? seg2 : seg1;
    const float* T   = set ? g_t2 : g_t1;
    float*       dout = set ? g_d2 : g_d1;
    __half*      hout = set ? g_h2 : g_h1;

    float sy = seg[line*4+0], sx = seg[line*4+1];
    float ey = seg[line*4+2], ex = seg[line*4+3];
    float dy = fs(ey, sy), dx = fs(ex, sx);
    float len = sqrtf(fa(fm(dy, dy), fm(dx, dx)));
    float ns  = fminf(fmaxf(floorf(__fdiv_rn(len, 8.0f)), 2.0f), 5.0f);
    if (k == 0 && lane == 0) g_ns[set][line] = ns;

    float nm1 = fs(ns, 1.0f);
    float ivy = __fdiv_rn(dy, nm1);
    float ivx = __fdiv_rn(dx, nm1);
    float kf  = (float)k;
    float py  = fa(sy, fm(kf, ivy));
    float px  = fa(sx, fm(kf, ivx));
    if (!(kf < ns)) { py = 0.0f; px = 0.0f; }

    float xn  = fs(__fdiv_rn(fm(2.0f, px), (float)(WW*4 - 1)), 1.0f);
    float yn  = fs(__fdiv_rn(fm(2.0f, py), (float)(HH*4 - 1)), 1.0f);
    float ixf = __fdiv_rn(fs(fm(fa(xn, 1.0f), (float)WW), 1.0f), 2.0f);
    float iyf = __fdiv_rn(fs(fm(fa(yn, 1.0f), (float)HH), 1.0f), 2.0f);
    float x0f = floorf(ixf), y0f = floorf(iyf);
    float wx = fs(ixf, x0f), wy = fs(iyf, y0f);
    int   x0 = (int)x0f,  y0 = (int)y0f;
    float w00 = fm(fs(1.0f, wx), fs(1.0f, wy));
    float w10 = fm(wx, fs(1.0f, wy));
    float w01 = fm(fs(1.0f, wx), wy);
    float w11 = fm(wx, wy);

    // corner bases in transposed layout (+ in-bounds flags)
    bool i00 = (x0   >= 0 && x0   < WW && y0   >= 0 && y0   < HH);
    bool i10 = (x0+1 >= 0 && x0+1 < WW && y0   >= 0 && y0   < HH);
    bool i01 = (x0   >= 0 && x0   < WW && y0+1 >= 0 && y0+1 < HH);
    bool i11 = (x0+1 >= 0 && x0+1 < WW && y0+1 >= 0 && y0+1 < HH);
    const float* p00 = T + ((size_t)(y0  )*WW + (x0  ))*DD;
    const float* p10 = T + ((size_t)(y0  )*WW + (x0+1))*DD;
    const float* p01 = T + ((size_t)(y0+1)*WW + (x0  ))*DD;
    const float* p11 = T + ((size_t)(y0+1)*WW + (x0+1))*DD;

    float v[4];
    float ss = 0.0f;
    #pragma unroll
    for (int q = 0; q < 4; q++) {
        int d = lane + q*32;
        float g00 = i00 ? p00[d] : 0.0f;
        float g10 = i10 ? p10[d] : 0.0f;
        float g01 = i01 ? p01[d] : 0.0f;
        float g11 = i11 ? p11[d] : 0.0f;
        float a = fm(g00, w00);
        a = fa(a, fm(g10, w10));
        a = fa(a, fm(g01, w01));
        a = fa(a, fm(g11, w11));
        v[q] = a;
        ss = fa(ss, fm(a, a));
    }
    #pragma unroll
    for (int off = 16; off; off >>= 1)
        ss = fa(ss, __shfl_xor_sync(0xffffffffu, ss, off));
    float nrm = sqrtf(ss);
    #pragma unroll
    for (int q = 0; q < 4; q++) {
        float val = __fdiv_rn(v[q], nrm);
        dout[p*DD + lane + q*32] = val;
        hout[p*DD + lane + q*32] = __float2half(val);
    }
}

// ------------- kernel 2: wmma fp16 GEMM -> APPROX line scores ----------------
#define SMEM_WMMA (2*128*LDT*2)   // A + B fp16  (== 128*LDT*4 for D overlay)

__global__ void ls_wmma_kernel() {
    extern __shared__ __align__(16) char smem[];
    __half* sA = (__half*)smem;
    __half* sB = sA + 128*LDT;
    float*  sD = (float*)smem;                   // overlay after compute

    const int t   = threadIdx.x;                 // 512
    const int wid = t >> 5;
    const int i0  = blockIdx.y * LPB;
    const int j0  = blockIdx.x * LPB;

    {
        const __half* Ap = g_h1 + (size_t)(i0*NS)*DD;
        const __half* Bp = g_h2 + (size_t)(j0*NS)*DD;
        #pragma unroll
        for (int it = 0; it < 8; it++) {
            int e = t + it*512;                  // 125*32 = 4000 8B-chunks
            if (e < 125*32) {
                int row = e >> 5, c4 = (e & 31) * 4;
                *(unsigned long long*)&sA[row*LDT + c4] =
                    *(const unsigned long long*)(Ap + row*DD + c4);
                *(unsigned long long*)&sB[row*LDT + c4] =
                    *(const unsigned long long*)(Bp + row*DD + c4);
            }
        }
    }
    __syncthreads();

    const int wr = (wid >> 2) * 32;
    const int wc = (wid & 3) * 32;
    wmma::fragment<wmma::accumulator, 16, 16, 16, float> acc[2][2];
    #pragma unroll
    for (int i = 0; i < 2; i++)
        #pragma unroll
        for (int j = 0; j < 2; j++) wmma::fill_fragment(acc[i][j], 0.0f);

    #pragma unroll
    for (int k0 = 0; k0 < DD; k0 += 16) {
        wmma::fragment<wmma::matrix_a, 16, 16, 16, __half, wmma::row_major> af[2];
        wmma::fragment<wmma::matrix_b, 16, 16, 16, __half, wmma::col_major> bf[2];
        #pragma unroll
        for (int i = 0; i < 2; i++)
            wmma::load_matrix_sync(af[i], &sA[(wr + i*16)*LDT + k0], LDT);
        #pragma unroll
        for (int j = 0; j < 2; j++)
            wmma::load_matrix_sync(bf[j], &sB[(wc + j*16)*LDT + k0], LDT);
        #pragma unroll
        for (int i = 0; i < 2; i++)
            #pragma unroll
            for (int j = 0; j < 2; j++)
                wmma::mma_sync(acc[i][j], af[i], bf[j], acc[i][j]);
    }
    __syncthreads();                             // A/B dead; overlay D
    #pragma unroll
    for (int i = 0; i < 2; i++)
        #pragma unroll
        for (int j = 0; j < 2; j++)
            wmma::store_matrix_sync(&sD[(wr + i*16)*LDT + wc + j*16],
                                    acc[i][j], LDT, wmma::mem_row_major);
    __syncthreads();

    for (int p = t; p < LPB*LPB; p += 512) {
        int li = p / LPB, lj = p - li*LPB;
        int nsa = (int)g_ns[0][i0 + li];
        int nsb = (int)g_ns[1][j0 + lj];
        const float* base = &sD[(li*NS)*LDT + lj*NS];

        float ls1s = 0.0f, c1 = 0.0f;
        #pragma unroll
        for (int n = 0; n < 5; n++) {
            float mx = -3.0e38f;
            #pragma unroll
            for (int m = 0; m < 5; m++) {
                float sv = (n < nsa && m < nsb) ? base[n*LDT + m] : -1.0f;
                mx = fmaxf(mx, sv);
            }
            float v1 = (mx != -1.0f) ? 1.0f : 0.0f;
            ls1s = fa(ls1s, fm(mx, v1)); c1 = fa(c1, v1);
        }
        float ls2s = 0.0f, c2 = 0.0f;
        #pragma unroll
        for (int m = 0; m < 5; m++) {
            float mx = -3.0e38f;
            #pragma unroll
            for (int n = 0; n < 5; n++) {
                float sv = (n < nsa && m < nsb) ? base[n*LDT + m] : -1.0f;
                mx = fmaxf(mx, sv);
            }
            float v2 = (mx != -1.0f) ? 1.0f : 0.0f;
            ls2s = fa(ls2s, fm(mx, v2)); c2 = fa(c2, v2);
        }
        float lsc = __fdiv_rn(fa(__fdiv_rn(ls1s, c1), __fdiv_rn(ls2s, c2)), 2.0f);
        g_ls [(i0+li)*NL + (j0+lj)] = lsc;
        g_lsT[(j0+lj)*NL + (i0+li)] = lsc;
    }
}

// -------- kernel 3: approx top-10 -> exact rescue -> top-10 + NW + argmax ----
__global__ void topk_rescue_kernel() {
    __shared__ unsigned long long sred[256];
    __shared__ __align__(16) float sA2[5][132];
    __shared__ __align__(16) float sB2[8][5][132];
    __shared__ int s_cand[NCAND_MAX];
    __shared__ float s_cex[NCAND_MAX];
    __shared__ int s_cnt;
    __shared__ int s_woff[8];
    __shared__ int s_top10[TK];
    __shared__ float s_nw[2*TK];

    int row = blockIdx.x, dir = blockIdx.y;
    int t = threadIdx.x;                   // 256
    int wid = t >> 5, lane = t & 31;
    const float* ls = dir ? g_lsT : g_ls;

    // Phase 1: 10-pass approx top-10 -> 10th value
    unsigned long long prev = 0xFFFFFFFFFFFFFFFFull;
    for (int s = 0; s < TK; s++) {
        unsigned long long best = 0ull;
        for (int j = t; j < NL; j += 256) {
            unsigned long long key =
                ((unsigned long long)enc_f(ls[row*NL + j]) << 32) | (unsigned)j;
            if (key < prev && key > best) best = key;
        }
        sred[t] = best;
        __syncthreads();
        #pragma unroll
        for (int off = 128; off; off >>= 1) {
            if (t < off) { if (sred[t+off] > sred[t]) sred[t] = sred[t+off]; }
            __syncthreads();
        }
        prev = sred[0];
        __syncthreads();
    }
    float tau = fs(dec_f((unsigned)(prev >> 32)), ERRB);

    // Phase 2: ordered, deterministic candidate compaction (ascending j)
    if (t == 0) s_cnt = 0;
    __syncthreads();
    for (int j0 = 0; j0 < NL; j0 += 256) {
        int j = j0 + t;
        bool pred = (j < NL) && (ls[row*NL + j] >= tau);
        unsigned bal = __ballot_sync(0xffffffffu, pred);
        if (lane == 0) s_woff[wid] = __popc(bal);
        __syncthreads();
        if (t == 0) {
            int b = s_cnt;
            #pragma unroll
            for (int w = 0; w < 8; w++) { int c = s_woff[w]; s_woff[w] = b; b += c; }
            s_cnt = b;
        }
        __syncthreads();
        if (pred) {
            int pos = s_woff[wid] + __popc(bal & ((1u << lane) - 1u));
            if (pos < NCAND_MAX) s_cand[pos] = j;
        }
        __syncthreads();
    }
    int ncand = min(s_cnt, NCAND_MAX);

    // Phase 3: exact line scores for candidates (bit-identical arithmetic)
    const float* dA = dir ? g_d2 : g_d1;
    const float* dB = dir ? g_d1 : g_d2;
    int nsa = (int)g_ns[dir][row];
    if (t < 160) {
        int r = t >> 5, c4 = t & 31;
        *(float4*)&sA2[r][c4*4] = *(const float4*)&dA[(row*NS + r)*DD + c4*4];
    }
    int n = lane / 5, m = lane - n*5;
    for (int base = 0; base < ncand; base += 8) {
        #pragma unroll
        for (int i = 0; i < 8; i++) {
            if (base + i < ncand && t < 160) {
                int j = s_cand[base + i];
                int r = t >> 5, c4 = t & 31;
                *(float4*)&sB2[i][r][c4*4] = *(const float4*)&dB[(j*NS + r)*DD + c4*4];
            }
        }
        __syncthreads();
        int c = base + wid;
        if (c < ncand) {
            int j = s_cand[c];
            int nsb = (int)g_ns[1-dir][j];
            float acc = 0.0f;
            if (lane < 25) {
                const float4* ra = (const float4*)&sA2[n][0];
                const float4* rb = (const float4*)&sB2[wid][m][0];
                #pragma unroll 8
                for (int k4 = 0; k4 < DD/4; k4++) {
                    float4 a = ra[k4];
                    float4 b = rb[k4];
                    acc = __fmaf_rn(a.x, b.x, acc);
                    acc = __fmaf_rn(a.y, b.y, acc);
                    acc = __fmaf_rn(a.z, b.z, acc);
                    acc = __fmaf_rn(a.w, b.w, acc);
                }
            }
            float blk[25];
            #pragma unroll
            for (int i = 0; i < 25; i++)
                blk[i] = __shfl_sync(0xffffffffu, acc, i);
            if (lane == 0) {
                float ls1s = 0.0f, c1 = 0.0f;
                #pragma unroll
                for (int nn = 0; nn < 5; nn++) {
                    float mx = -3.0e38f;
                    #pragma unroll
                    for (int mm = 0; mm < 5; mm++) {
                        float sv = (nn < nsa && mm < nsb) ? blk[nn*5 + mm] : -1.0f;
                        mx = fmaxf(mx, sv);
                    }
                    float v1 = (mx != -1.0f) ? 1.0f : 0.0f;
                    ls1s = fa(ls1s, fm(mx, v1)); c1 = fa(c1, v1);
                }
                float ls2s = 0.0f, c2 = 0.0f;
                #pragma unroll
                for (int mm = 0; mm < 5; mm++) {
                    float mx = -3.0e38f;
                    #pragma unroll
                    for (int nn = 0; nn < 5; nn++) {
                        float sv = (nn < nsa && mm < nsb) ? blk[nn*5 + mm] : -1.0f;
                        mx = fmaxf(mx, sv);
                    }
                    float v2 = (mx != -1.0f) ? 1.0f : 0.0f;
                    ls2s = fa(ls2s, fm(mx, v2)); c2 = fa(c2, v2);
                }
                s_cex[c] = __fdiv_rn(fa(__fdiv_rn(ls1s, c1), __fdiv_rn(ls2s, c2)), 2.0f);
            }
        }
        __syncthreads();
    }

    // Phase 4: exact top-10 among candidates (same argsort-key semantics)
    if (wid == 0) {
        unsigned long long prv = 0xFFFFFFFFFFFFFFFFull;
        for (int s = 0; s < TK; s++) {
            unsigned long long best = 0ull;
            for (int c = lane; c < ncand; c += 32) {
                unsigned long long key =
                    ((unsigned long long)enc_f(s_cex[c]) << 32) | (unsigned)s_cand[c];
                if (key < prv && key > best) best = key;
            }
            #pragma unroll
            for (int off = 16; off; off >>= 1) {
                unsigned long long o = __shfl_xor_sync(0xffffffffu, best, off);
                if (o > best) best = o;
            }
            prv = best;
            if (lane == 0) {
                int j = (int)(best & 0xFFFFFFFFull);
                g_topk[dir][row*TK + (TK-1-s)] = j;
                s_top10[TK-1-s] = j;
            }
        }
    }
    __syncthreads();

    // Phase 5: NW DP for top-10 (dots recomputed bit-identically; A from smem,
    // B rows from gmem) + write g_nw
    for (int c = wid; c < TK; c += 8) {
        int j = s_top10[c];
        int nb = (int)g_ns[1-dir][j];
        float acc = 0.0f;
        if (lane < 25) {
            const float4* ra = (const float4*)&sA2[n][0];
            const float4* rb = (const float4*)&dB[(j*NS + m)*DD];
            #pragma unroll 8
            for (int k4 = 0; k4 < DD/4; k4++) {
                float4 a = ra[k4];
                float4 b = rb[k4];
                acc = __fmaf_rn(a.x, b.x, acc);
                acc = __fmaf_rn(a.y, b.y, acc);
                acc = __fmaf_rn(a.z, b.z, acc);
                acc = __fmaf_rn(a.w, b.w, acc);
            }
        }
        float blk[25];
        #pragma unroll
        for (int i = 0; i < 25; i++)
            blk[i] = __shfl_sync(0xffffffffu, acc, i);

        if (lane < 2) {
            int flip = lane;
            float prev5[6] = {0,0,0,0,0,0};
            #pragma unroll
            for (int r = 0; r < 5; r++) {
                float cur[6]; cur[0] = 0.0f;
                #pragma unroll
                for (int cI = 0; cI < 5; cI++) {
                    int sm = flip ? (4 - cI) : cI;
                    float sv = (r < nsa && sm < nb) ? blk[r*5 + sm] : -1.0f;
                    sv = fs(sv, GAPF);
                    cur[cI+1] = fmaxf(fmaxf(cur[cI], prev5[cI+1]), fa(prev5[cI], sv));
                }
                #pragma unroll
                for (int cI = 0; cI < 6; cI++) prev5[cI] = cur[cI];
            }
            g_nw[dir][row*2*TK + flip*TK + c] = prev5[5];
            s_nw[flip*TK + c] = prev5[5];
        }
    }
    __syncthreads();

    // Phase 6: argmax over 20 (first-occurrence, same order as reference)
    if (t == 0) {
        float best = s_nw[0]; int bi = 0;
        for (int q = 1; q < 2*TK; q++)
            if (s_nw[q] > best) { best = s_nw[q]; bi = q; }
        g_match[dir][row] = s_top10[bi % TK];
    }
}

// ---------------- kernel 4: mutual check + write output ----------------------
__global__ void final_kernel(float* __restrict__ out, int out_size) {
    int idx = blockIdx.x * blockDim.x + threadIdx.x;
    if (idx >= NL + NL*2*TK || idx >= out_size) return;
    if (idx < NL) {
        int m  = g_match[0][idx];
        int ok = (g_match[1][m] == idx);
        out[idx] = ok ? (float)m : -1.0f;
    } else {
        out[idx] = g_nw[0][idx - NL];
    }
}

// ---------------- launcher ---------------------------------------------------
extern "C" void kernel_launch(void* const* d_in, const int* in_sizes, int n_in,
                              void* d_out, int out_size) {
    const float* seg1  = (const float*)d_in[0];
    const float* seg2  = (const float*)d_in[1];
    const float* desc1 = (const float*)d_in[2];
    const float* desc2 = (const float*)d_in[3];

    static int smem_set = 0;
    if (!smem_set) {
        cudaFuncSetAttribute(ls_wmma_kernel,
                             cudaFuncAttributeMaxDynamicSharedMemorySize, SMEM_WMMA);
        smem_set = 1;
    }

    transpose_kernel<<<dim3(WW/32, DD/32, 2*HH), dim3(32, 8)>>>(desc1, desc2);
    {
        int warps = 2*NPTS;
        int threads = warps*32;
        sample_kernel<<<(threads + 255)/256, 256>>>(seg1, seg2);
    }
    ls_wmma_kernel<<<dim3(NL/LPB, NL/LPB), 512, SMEM_WMMA>>>();
    topk_rescue_kernel<<<dim3(NL, 2), 256>>>();
    final_kernel<<<(NL + NL*2*TK + 255)/256, 256>>>((float*)d_out, out_size);
}

// round 13
// speedup vs baseline: 1.1568x; 1.1568x over previous
#include <cuda_runtime.h>
#include <cuda_fp16.h>
#include <mma.h>
#include <math.h>
#include <cstdint>

using namespace nvcuda;

#define NL   1200
#define NS   5
#define NPTS (NL*NS)      // 6000
#define DD   128
#define HH   128
#define WW   128
#define TK   10
#define GAPF 0.1f
#define NCAND_MAX 320
#define ERRB 0.0022f      // > 2 * fp16 dot error bound (2*9.8e-4)

#define LPB  25           // lines per tile side (25*5 = 125 rows of a 128 tile)
#define LDT  136          // smem leading dim, mult of 8

// ---------------- scratch (static __device__, no allocations) ----------------
static __device__ float g_d1[NPTS*DD];            // exact normalized descriptors
static __device__ float g_d2[NPTS*DD];
static __device__ __half g_h1[NPTS*DD];           // fp16 copies (same layout)
static __device__ __half g_h2[NPTS*DD];
static __device__ float g_t1[HH*WW*DD];           // desc transposed [y][x][d]
static __device__ float g_t2[HH*WW*DD];
static __device__ float g_ns[2][NL];
static __device__ float g_ls [NL*NL];             // APPROX line scores
static __device__ float g_lsT[NL*NL];
static __device__ int   g_topk[2][NL*TK];         // exact top-10, argsort order
static __device__ float g_nw [2][NL*2*TK];
static __device__ int   g_match[2][NL];

// Unfused helpers (match XLA's per-op rounding; no FMA contraction)
__device__ __forceinline__ float fm(float a, float b) { return __fmul_rn(a, b); }
__device__ __forceinline__ float fa(float a, float b) { return __fadd_rn(a, b); }
__device__ __forceinline__ float fs(float a, float b) { return __fsub_rn(a, b); }

// monotonic float<->uint for argsort-compatible keys
__device__ __forceinline__ unsigned enc_f(float v) {
    unsigned u = __float_as_uint(v);
    return (u & 0x80000000u) ? ~u : (u | 0x80000000u);
}
__device__ __forceinline__ float dec_f(unsigned u) {
    unsigned o = (u >> 31) ? (u & 0x7FFFFFFFu) : ~u;
    return __uint_as_float(o);
}

// ---------------- kernel 0: transpose desc [d][y][x] -> [y][x][d] ------------
__global__ void transpose_kernel(const float* __restrict__ desc1,
                                 const float* __restrict__ desc2) {
    __shared__ float tile[32][33];
    int z   = blockIdx.z;
    int set = z >> 7;                   // 0..1
    int y   = z & 127;
    const float* src = set ? desc2 : desc1;
    float*       dst = set ? g_t2  : g_t1;
    int d0 = blockIdx.y * 32;
    int x0 = blockIdx.x * 32;
    int tx = threadIdx.x, ty = threadIdx.y;   // 32 x 8
    #pragma unroll
    for (int i = 0; i < 32; i += 8)
        tile[ty+i][tx] = src[(d0+ty+i)*HH*WW + y*WW + x0+tx];
    __syncthreads();
    #pragma unroll
    for (int i = 0; i < 32; i += 8)
        dst[(y*WW + x0+ty+i)*DD + d0+tx] = tile[tx][ty+i];
}

// ---------------- kernel 1: sample points + bilinear descriptors -------------
// Gathers from the transposed layout: for a fixed corner, lane d reads
// consecutive floats -> fully coalesced. Arithmetic identical to before.
__global__ void sample_kernel(const float* __restrict__ seg1,
                              const float* __restrict__ seg2) {
    int warp = (blockIdx.x * blockDim.x + threadIdx.x) >> 5;
    int lane = threadIdx.x & 31;
    if (warp >= 2*NPTS) return;
    int set  = warp / NPTS;
    int p    = warp - set*NPTS;
    int line = p / NS;
    int k    = p - line*NS;

    const float* seg = set ? seg2 : seg1;
    const float* T   = set ? g_t2 : g_t1;
    float*       dout = set ? g_d2 : g_d1;
    __half*      hout = set ? g_h2 : g_h1;

    float sy = seg[line*4+0], sx = seg[line*4+1];
    float ey = seg[line*4+2], ex = seg[line*4+3];
    float dy = fs(ey, sy), dx = fs(ex, sx);
    float len = sqrtf(fa(fm(dy, dy), fm(dx, dx)));
    float ns  = fminf(fmaxf(floorf(__fdiv_rn(len, 8.0f)), 2.0f), 5.0f);
    if (k == 0 && lane == 0) g_ns[set][line] = ns;

    float nm1 = fs(ns, 1.0f);
    float ivy = __fdiv_rn(dy, nm1);
    float ivx = __fdiv_rn(dx, nm1);
    float kf  = (float)k;
    float py  = fa(sy, fm(kf, ivy));
    float px  = fa(sx, fm(kf, ivx));
    if (!(kf < ns)) { py = 0.0f; px = 0.0f; }

    float xn  = fs(__fdiv_rn(fm(2.0f, px), (float)(WW*4 - 1)), 1.0f);
    float yn  = fs(__fdiv_rn(fm(2.0f, py), (float)(HH*4 - 1)), 1.0f);
    float ixf = __fdiv_rn(fs(fm(fa(xn, 1.0f), (float)WW), 1.0f), 2.0f);
    float iyf = __fdiv_rn(fs(fm(fa(yn, 1.0f), (float)HH), 1.0f), 2.0f);
    float x0f = floorf(ixf), y0f = floorf(iyf);
    float wx = fs(ixf, x0f), wy = fs(iyf, y0f);
    int   x0 = (int)x0f,  y0 = (int)y0f;
    float w00 = fm(fs(1.0f, wx), fs(1.0f, wy));
    float w10 = fm(wx, fs(1.0f, wy));
    float w01 = fm(fs(1.0f, wx), wy);
    float w11 = fm(wx, wy);

    bool i00 = (x0   >= 0 && x0   < WW && y0   >= 0 && y0   < HH);
    bool i10 = (x0+1 >= 0 && x0+1 < WW && y0   >= 0 && y0   < HH);
    bool i01 = (x0   >= 0 && x0   < WW && y0+1 >= 0 && y0+1 < HH);
    bool i11 = (x0+1 >= 0 && x0+1 < WW && y0+1 >= 0 && y0+1 < HH);
    const float* p00 = T + ((size_t)(y0  )*WW + (x0  ))*DD;
    const float* p10 = T + ((size_t)(y0  )*WW + (x0+1))*DD;
    const float* p01 = T + ((size_t)(y0+1)*WW + (x0  ))*DD;
    const float* p11 = T + ((size_t)(y0+1)*WW + (x0+1))*DD;

    float v[4];
    float ss = 0.0f;
    #pragma unroll
    for (int q = 0; q < 4; q++) {
        int d = lane + q*32;
        float g00 = i00 ? p00[d] : 0.0f;
        float g10 = i10 ? p10[d] : 0.0f;
        float g01 = i01 ? p01[d] : 0.0f;
        float g11 = i11 ? p11[d] : 0.0f;
        float a = fm(g00, w00);
        a = fa(a, fm(g10, w10));
        a = fa(a, fm(g01, w01));
        a = fa(a, fm(g11, w11));
        v[q] = a;
        ss = fa(ss, fm(a, a));
    }
    #pragma unroll
    for (int off = 16; off; off >>= 1)
        ss = fa(ss, __shfl_xor_sync(0xffffffffu, ss, off));
    float nrm = sqrtf(ss);
    #pragma unroll
    for (int q = 0; q < 4; q++) {
        float val = __fdiv_rn(v[q], nrm);
        dout[p*DD + lane + q*32] = val;
        hout[p*DD + lane + q*32] = __float2half(val);
    }
}

// ------------- kernel 2: wmma fp16 GEMM -> APPROX line scores ----------------
#define SMEM_WMMA (2*128*LDT*2)   // A + B fp16  (== 128*LDT*4 for D overlay)

__global__ void ls_wmma_kernel() {
    extern __shared__ __align__(16) char smem[];
    __half* sA = (__half*)smem;
    __half* sB = sA + 128*LDT;
    float*  sD = (float*)smem;                   // overlay after compute

    const int t   = threadIdx.x;                 // 512
    const int wid = t >> 5;
    const int i0  = blockIdx.y * LPB;
    const int j0  = blockIdx.x * LPB;

    {
        const __half* Ap = g_h1 + (size_t)(i0*NS)*DD;
        const __half* Bp = g_h2 + (size_t)(j0*NS)*DD;
        #pragma unroll
        for (int it = 0; it < 8; it++) {
            int e = t + it*512;                  // 125*32 = 4000 8B-chunks
            if (e < 125*32) {
                int row = e >> 5, c4 = (e & 31) * 4;
                *(unsigned long long*)&sA[row*LDT + c4] =
                    *(const unsigned long long*)(Ap + row*DD + c4);
                *(unsigned long long*)&sB[row*LDT + c4] =
                    *(const unsigned long long*)(Bp + row*DD + c4);
            }
        }
    }
    __syncthreads();

    const int wr = (wid >> 2) * 32;
    const int wc = (wid & 3) * 32;
    wmma::fragment<wmma::accumulator, 16, 16, 16, float> acc[2][2];
    #pragma unroll
    for (int i = 0; i < 2; i++)
        #pragma unroll
        for (int j = 0; j < 2; j++) wmma::fill_fragment(acc[i][j], 0.0f);

    #pragma unroll
    for (int k0 = 0; k0 < DD; k0 += 16) {
        wmma::fragment<wmma::matrix_a, 16, 16, 16, __half, wmma::row_major> af[2];
        wmma::fragment<wmma::matrix_b, 16, 16, 16, __half, wmma::col_major> bf[2];
        #pragma unroll
        for (int i = 0; i < 2; i++)
            wmma::load_matrix_sync(af[i], &sA[(wr + i*16)*LDT + k0], LDT);
        #pragma unroll
        for (int j = 0; j < 2; j++)
            wmma::load_matrix_sync(bf[j], &sB[(wc + j*16)*LDT + k0], LDT);
        #pragma unroll
        for (int i = 0; i < 2; i++)
            #pragma unroll
            for (int j = 0; j < 2; j++)
                wmma::mma_sync(acc[i][j], af[i], bf[j], acc[i][j]);
    }
    __syncthreads();                             // A/B dead; overlay D
    #pragma unroll
    for (int i = 0; i < 2; i++)
        #pragma unroll
        for (int j = 0; j < 2; j++)
            wmma::store_matrix_sync(&sD[(wr + i*16)*LDT + wc + j*16],
                                    acc[i][j], LDT, wmma::mem_row_major);
    __syncthreads();

    for (int p = t; p < LPB*LPB; p += 512) {
        int li = p / LPB, lj = p - li*LPB;
        int nsa = (int)g_ns[0][i0 + li];
        int nsb = (int)g_ns[1][j0 + lj];
        const float* base = &sD[(li*NS)*LDT + lj*NS];

        float ls1s = 0.0f, c1 = 0.0f;
        #pragma unroll
        for (int n = 0; n < 5; n++) {
            float mx = -3.0e38f;
            #pragma unroll
            for (int m = 0; m < 5; m++) {
                float sv = (n < nsa && m < nsb) ? base[n*LDT + m] : -1.0f;
                mx = fmaxf(mx, sv);
            }
            float v1 = (mx != -1.0f) ? 1.0f : 0.0f;
            ls1s = fa(ls1s, fm(mx, v1)); c1 = fa(c1, v1);
        }
        float ls2s = 0.0f, c2 = 0.0f;
        #pragma unroll
        for (int m = 0; m < 5; m++) {
            float mx = -3.0e38f;
            #pragma unroll
            for (int n = 0; n < 5; n++) {
                float sv = (n < nsa && m < nsb) ? base[n*LDT + m] : -1.0f;
                mx = fmaxf(mx, sv);
            }
            float v2 = (mx != -1.0f) ? 1.0f : 0.0f;
            ls2s = fa(ls2s, fm(mx, v2)); c2 = fa(c2, v2);
        }
        float lsc = __fdiv_rn(fa(__fdiv_rn(ls1s, c1), __fdiv_rn(ls2s, c2)), 2.0f);
        g_ls [(i0+li)*NL + (j0+lj)] = lsc;
        g_lsT[(j0+lj)*NL + (i0+li)] = lsc;
    }
}

// -------- kernel 3: approx top-10 -> exact rescue -> exact top-10 ------------
__global__ void topk_rescue_kernel() {
    __shared__ unsigned long long sred[8];
    __shared__ unsigned long long s_prev;
    __shared__ __align__(16) float sA2[5][132];
    __shared__ __align__(16) float sB2[8][5][132];
    __shared__ int s_cand[NCAND_MAX];
    __shared__ float s_cex[NCAND_MAX];
    __shared__ int s_cnt;
    __shared__ int s_woff[8];

    int row = blockIdx.x, dir = blockIdx.y;
    int t = threadIdx.x;                   // 256
    int wid = t >> 5, lane = t & 31;
    const float* ls = dir ? g_lsT : g_ls;

    // Phase 1: 10-pass approx top-10 -> 10th value.
    // Max over unique u64 keys is order-invariant -> warp shfl + 8-way final.
    unsigned long long prev = 0xFFFFFFFFFFFFFFFFull;
    for (int s = 0; s < TK; s++) {
        unsigned long long best = 0ull;
        for (int j = t; j < NL; j += 256) {
            unsigned long long key =
                ((unsigned long long)enc_f(ls[row*NL + j]) << 32) | (unsigned)j;
            if (key < prev && key > best) best = key;
        }
        #pragma unroll
        for (int off = 16; off; off >>= 1) {
            unsigned long long o = __shfl_xor_sync(0xffffffffu, best, off);
            if (o > best) best = o;
        }
        if (lane == 0) sred[wid] = best;
        __syncthreads();
        if (t == 0) {
            unsigned long long b = sred[0];
            #pragma unroll
            for (int w = 1; w < 8; w++) if (sred[w] > b) b = sred[w];
            s_prev = b;
        }
        __syncthreads();
        prev = s_prev;
    }
    float tau = fs(dec_f((unsigned)(prev >> 32)), ERRB);

    // Phase 2: ordered, deterministic candidate compaction (ascending j)
    if (t == 0) s_cnt = 0;
    __syncthreads();
    for (int j0 = 0; j0 < NL; j0 += 256) {
        int j = j0 + t;
        bool pred = (j < NL) && (ls[row*NL + j] >= tau);
        unsigned bal = __ballot_sync(0xffffffffu, pred);
        if (lane == 0) s_woff[wid] = __popc(bal);
        __syncthreads();
        if (t == 0) {
            int b = s_cnt;
            #pragma unroll
            for (int w = 0; w < 8; w++) { int c = s_woff[w]; s_woff[w] = b; b += c; }
            s_cnt = b;
        }
        __syncthreads();
        if (pred) {
            int pos = s_woff[wid] + __popc(bal & ((1u << lane) - 1u));
            if (pos < NCAND_MAX) s_cand[pos] = j;
        }
        __syncthreads();
    }
    int ncand = min(s_cnt, NCAND_MAX);

    // Phase 3: exact line scores for candidates (bit-identical arithmetic)
    const float* dA = dir ? g_d2 : g_d1;
    const float* dB = dir ? g_d1 : g_d2;
    int nsa = (int)g_ns[dir][row];
    if (t < 160) {
        int r = t >> 5, c4 = t & 31;
        *(float4*)&sA2[r][c4*4] = *(const float4*)&dA[(row*NS + r)*DD + c4*4];
    }
    int n = lane / 5, m = lane - n*5;
    for (int base = 0; base < ncand; base += 8) {
        #pragma unroll
        for (int i = 0; i < 8; i++) {
            if (base + i < ncand && t < 160) {
                int j = s_cand[base + i];
                int r = t >> 5, c4 = t & 31;
                *(float4*)&sB2[i][r][c4*4] = *(const float4*)&dB[(j*NS + r)*DD + c4*4];
            }
        }
        __syncthreads();
        int c = base + wid;
        if (c < ncand) {
            int j = s_cand[c];
            int nsb = (int)g_ns[1-dir][j];
            float acc = 0.0f;
            if (lane < 25) {
                const float4* ra = (const float4*)&sA2[n][0];
                const float4* rb = (const float4*)&sB2[wid][m][0];
                #pragma unroll 8
                for (int k4 = 0; k4 < DD/4; k4++) {
                    float4 a = ra[k4];
                    float4 b = rb[k4];
                    acc = __fmaf_rn(a.x, b.x, acc);
                    acc = __fmaf_rn(a.y, b.y, acc);
                    acc = __fmaf_rn(a.z, b.z, acc);
                    acc = __fmaf_rn(a.w, b.w, acc);
                }
            }
            float blk[25];
            #pragma unroll
            for (int i = 0; i < 25; i++)
                blk[i] = __shfl_sync(0xffffffffu, acc, i);
            if (lane == 0) {
                float ls1s = 0.0f, c1 = 0.0f;
                #pragma unroll
                for (int nn = 0; nn < 5; nn++) {
                    float mx = -3.0e38f;
                    #pragma unroll
                    for (int mm = 0; mm < 5; mm++) {
                        float sv = (nn < nsa && mm < nsb) ? blk[nn*5 + mm] : -1.0f;
                        mx = fmaxf(mx, sv);
                    }
                    float v1 = (mx != -1.0f) ? 1.0f : 0.0f;
                    ls1s = fa(ls1s, fm(mx, v1)); c1 = fa(c1, v1);
                }
                float ls2s = 0.0f, c2 = 0.0f;
                #pragma unroll
                for (int mm = 0; mm < 5; mm++) {
                    float mx = -3.0e38f;
                    #pragma unroll
                    for (int nn = 0; nn < 5; nn++) {
                        float sv = (nn < nsa && mm < nsb) ? blk[nn*5 + mm] : -1.0f;
                        mx = fmaxf(mx, sv);
                    }
                    float v2 = (mx != -1.0f) ? 1.0f : 0.0f;
                    ls2s = fa(ls2s, fm(mx, v2)); c2 = fa(c2, v2);
                }
                s_cex[c] = __fdiv_rn(fa(__fdiv_rn(ls1s, c1), __fdiv_rn(ls2s, c2)), 2.0f);
            }
        }
        __syncthreads();
    }

    // Phase 4: exact top-10 among candidates (same argsort-key semantics)
    if (wid == 0) {
        unsigned long long prv = 0xFFFFFFFFFFFFFFFFull;
        for (int s = 0; s < TK; s++) {
            unsigned long long best = 0ull;
            for (int c = lane; c < ncand; c += 32) {
                unsigned long long key =
                    ((unsigned long long)enc_f(s_cex[c]) << 32) | (unsigned)s_cand[c];
                if (key < prv && key > best) best = key;
            }
            #pragma unroll
            for (int off = 16; off; off >>= 1) {
                unsigned long long o = __shfl_xor_sync(0xffffffffu, best, off);
                if (o > best) best = o;
            }
            prv = best;
            if (lane == 0) g_topk[dir][row*TK + (TK-1-s)] = (int)(best & 0xFFFFFFFFull);
        }
    }
}

// ---------------- kernel 4: smem-staged 5x5 blocks + Needleman-Wunsch --------
__global__ void nw_kernel() {
    __shared__ __align__(16) float sA[5][132];
    __shared__ __align__(16) float sB[10][5][132];
    __shared__ int s_top[10];
    int line = blockIdx.x;
    int dir  = blockIdx.y;
    int t    = threadIdx.x;                 // 160

    const float* dA = dir ? g_d2 : g_d1;
    const float* dB = dir ? g_d1 : g_d2;

    if (t < 10) s_top[t] = g_topk[dir][line*TK + t];
    __syncthreads();

    {
        int r = t >> 5, c4 = t & 31;
        *(float4*)&sA[r][c4*4] = *(const float4*)&dA[(line*NS + r)*DD + c4*4];
    }
    #pragma unroll
    for (int i = 0; i < 10; i++) {
        int j = s_top[i];
        int r = t >> 5, c4 = t & 31;
        *(float4*)&sB[i][r][c4*4] = *(const float4*)&dB[(j*NS + r)*DD + c4*4];
    }
    __syncthreads();

    int warp = t >> 5, lane = t & 31;
    int na = (int)g_ns[dir][line];
    int n = lane / 5, m = lane - n*5;

    #pragma unroll
    for (int cc = 0; cc < 2; cc++) {
        int c = warp*2 + cc;
        int j = s_top[c];
        int nb = (int)g_ns[1-dir][j];

        float acc = 0.0f;
        if (lane < 25) {
            const float4* ra = (const float4*)&sA[n][0];
            const float4* rb = (const float4*)&sB[c][m][0];
            #pragma unroll 8
            for (int k4 = 0; k4 < DD/4; k4++) {
                float4 a = ra[k4];
                float4 b = rb[k4];
                acc = __fmaf_rn(a.x, b.x, acc);
                acc = __fmaf_rn(a.y, b.y, acc);
                acc = __fmaf_rn(a.z, b.z, acc);
                acc = __fmaf_rn(a.w, b.w, acc);
            }
        }
        float blk[25];
        #pragma unroll
        for (int i = 0; i < 25; i++)
            blk[i] = __shfl_sync(0xffffffffu, acc, i);

        if (lane < 2) {
            int flip = lane;
            float prev[6] = {0,0,0,0,0,0};
            #pragma unroll
            for (int r = 0; r < 5; r++) {
                float cur[6]; cur[0] = 0.0f;
                #pragma unroll
                for (int cI = 0; cI < 5; cI++) {
                    int sm = flip ? (4 - cI) : cI;
                    float sv = (r < na && sm < nb) ? blk[r*5 + sm] : -1.0f;
                    sv = fs(sv, GAPF);
                    cur[cI+1] = fmaxf(fmaxf(cur[cI], prev[cI+1]), fa(prev[cI], sv));
                }
                #pragma unroll
                for (int cI = 0; cI < 6; cI++) prev[cI] = cur[cI];
            }
            g_nw[dir][line*2*TK + flip*TK + c] = prev[5];
        }
    }
}

// ---------------- kernel 5: argmax over 20 candidates ------------------------
__global__ void argmax_kernel() {
    int idx = blockIdx.x * blockDim.x + threadIdx.x;
    if (idx >= 2*NL) return;
    int dir = idx / NL, line = idx - dir*NL;
    const float* nw = &g_nw[dir][line*2*TK];
    float best = nw[0]; int bi = 0;
    for (int t = 1; t < 2*TK; t++)
        if (nw[t] > best) { best = nw[t]; bi = t; }
    g_match[dir][line] = g_topk[dir][line*TK + (bi % TK)];
}

// ---------------- kernel 6: mutual check + write output ----------------------
__global__ void final_kernel(float* __restrict__ out, int out_size) {
    int idx = blockIdx.x * blockDim.x + threadIdx.x;
    if (idx >= NL + NL*2*TK || idx >= out_size) return;
    if (idx < NL) {
        int m  = g_match[0][idx];
        int ok = (g_match[1][m] == idx);
        out[idx] = ok ? (float)m : -1.0f;
    } else {
        out[idx] = g_nw[0][idx - NL];
    }
}

// ---------------- launcher ---------------------------------------------------
extern "C" void kernel_launch(void* const* d_in, const int* in_sizes, int n_in,
                              void* d_out, int out_size) {
    const float* seg1  = (const float*)d_in[0];
    const float* seg2  = (const float*)d_in[1];
    const float* desc1 = (const float*)d_in[2];
    const float* desc2 = (const float*)d_in[3];

    static int smem_set = 0;
    if (!smem_set) {
        cudaFuncSetAttribute(ls_wmma_kernel,
                             cudaFuncAttributeMaxDynamicSharedMemorySize, SMEM_WMMA);
        smem_set = 1;
    }

    transpose_kernel<<<dim3(WW/32, DD/32, 2*HH), dim3(32, 8)>>>(desc1, desc2);
    {
        int warps = 2*NPTS;
        int threads = warps*32;
        sample_kernel<<<(threads + 255)/256, 256>>>(seg1, seg2);
    }
    ls_wmma_kernel<<<dim3(NL/LPB, NL/LPB), 512, SMEM_WMMA>>>();
    topk_rescue_kernel<<<dim3(NL, 2), 256>>>();
    nw_kernel<<<dim3(NL, 2), 160>>>();
    argmax_kernel<<<(2*NL + 255)/256, 256>>>();
    final_kernel<<<(NL + NL*2*TK + 255)/256, 256>>>((float*)d_out, out_size);
}

// round 14
// speedup vs baseline: 1.7023x; 1.4715x over previous
#include <cuda_runtime.h>
#include <cuda_fp16.h>
#include <mma.h>
#include <math.h>
#include <cstdint>

using namespace nvcuda;

#define NL   1200
#define NS   5
#define NPTS (NL*NS)      // 6000
#define DD   128
#define HH   128
#define WW   128
#define TK   10
#define GAPF 0.1f
#define NCAND_MAX 320
#define ERRB 0.0022f      // > 2 * fp16 dot error bound (2*9.8e-4)

#define LPB  25           // lines per tile side (25*5 = 125 rows of a 128 tile)
#define LDT  136          // smem leading dim, mult of 8

// ---------------- scratch (static __device__, no allocations) ----------------
static __device__ float g_d1[NPTS*DD];            // exact normalized descriptors
static __device__ float g_d2[NPTS*DD];
static __device__ __half g_h1[NPTS*DD];           // fp16 copies (same layout)
static __device__ __half g_h2[NPTS*DD];
static __device__ float g_ns[2][NL];
static __device__ float g_ls [NL*NL];             // APPROX line scores
static __device__ float g_lsT[NL*NL];
static __device__ int   g_topk[2][NL*TK];         // exact top-10, argsort order
static __device__ float g_nw [2][NL*2*TK];
static __device__ int   g_match[2][NL];

// Unfused helpers (match XLA's per-op rounding; no FMA contraction)
__device__ __forceinline__ float fm(float a, float b) { return __fmul_rn(a, b); }
__device__ __forceinline__ float fa(float a, float b) { return __fadd_rn(a, b); }
__device__ __forceinline__ float fs(float a, float b) { return __fsub_rn(a, b); }

// monotonic float<->uint for argsort-compatible keys
__device__ __forceinline__ unsigned enc_f(float v) {
    unsigned u = __float_as_uint(v);
    return (u & 0x80000000u) ? ~u : (u | 0x80000000u);
}
__device__ __forceinline__ float dec_f(unsigned u) {
    unsigned o = (u >> 31) ? (u & 0x7FFFFFFFu) : ~u;
    return __uint_as_float(o);
}

// ---------------- kernel 1: sample points + bilinear descriptors -------------
__device__ __forceinline__ float gat(const float* img, int x, int y) {
    if (x < 0 || x >= WW || y < 0 || y >= HH) return 0.0f;
    return img[y*WW + x];
}

__global__ void sample_kernel(const float* __restrict__ seg1,
                              const float* __restrict__ seg2,
                              const float* __restrict__ desc1,
                              const float* __restrict__ desc2) {
    int warp = (blockIdx.x * blockDim.x + threadIdx.x) >> 5;
    int lane = threadIdx.x & 31;
    if (warp >= 2*NPTS) return;
    int set  = warp / NPTS;
    int p    = warp - set*NPTS;
    int line = p / NS;
    int k    = p - line*NS;

    const float* seg  = set ? seg2  : seg1;
    const float* desc = set ? desc2 : desc1;
    float*       dout = set ? g_d2  : g_d1;
    __half*      hout = set ? g_h2  : g_h1;

    float sy = seg[line*4+0], sx = seg[line*4+1];
    float ey = seg[line*4+2], ex = seg[line*4+3];
    float dy = fs(ey, sy), dx = fs(ex, sx);
    float len = sqrtf(fa(fm(dy, dy), fm(dx, dx)));
    float ns  = fminf(fmaxf(floorf(__fdiv_rn(len, 8.0f)), 2.0f), 5.0f);
    if (k == 0 && lane == 0) g_ns[set][line] = ns;

    float nm1 = fs(ns, 1.0f);
    float ivy = __fdiv_rn(dy, nm1);
    float ivx = __fdiv_rn(dx, nm1);
    float kf  = (float)k;
    float py  = fa(sy, fm(kf, ivy));
    float px  = fa(sx, fm(kf, ivx));
    if (!(kf < ns)) { py = 0.0f; px = 0.0f; }

    float xn  = fs(__fdiv_rn(fm(2.0f, px), (float)(WW*4 - 1)), 1.0f);
    float yn  = fs(__fdiv_rn(fm(2.0f, py), (float)(HH*4 - 1)), 1.0f);
    float ixf = __fdiv_rn(fs(fm(fa(xn, 1.0f), (float)WW), 1.0f), 2.0f);
    float iyf = __fdiv_rn(fs(fm(fa(yn, 1.0f), (float)HH), 1.0f), 2.0f);
    float x0f = floorf(ixf), y0f = floorf(iyf);
    float wx = fs(ixf, x0f), wy = fs(iyf, y0f);
    int   x0 = (int)x0f,  y0 = (int)y0f;
    float w00 = fm(fs(1.0f, wx), fs(1.0f, wy));
    float w10 = fm(wx, fs(1.0f, wy));
    float w01 = fm(fs(1.0f, wx), wy);
    float w11 = fm(wx, wy);

    float v[4];
    float ss = 0.0f;
    #pragma unroll
    for (int q = 0; q < 4; q++) {
        int d = lane + q*32;
        const float* img = desc + d*HH*WW;
        float a = fm(gat(img, x0,   y0  ), w00);
        a = fa(a, fm(gat(img, x0+1, y0  ), w10));
        a = fa(a, fm(gat(img, x0,   y0+1), w01));
        a = fa(a, fm(gat(img, x0+1, y0+1), w11));
        v[q] = a;
        ss = fa(ss, fm(a, a));
    }
    #pragma unroll
    for (int off = 16; off; off >>= 1)
        ss = fa(ss, __shfl_xor_sync(0xffffffffu, ss, off));
    float nrm = sqrtf(ss);
    #pragma unroll
    for (int q = 0; q < 4; q++) {
        float val = __fdiv_rn(v[q], nrm);
        dout[p*DD + lane + q*32] = val;
        hout[p*DD + lane + q*32] = __float2half(val);
    }
}

// ------------- kernel 2: wmma fp16 GEMM -> APPROX line scores ----------------
// Block = 25x25 lines = 125x125 samples inside a 128x128 wmma tile. 512 thr =
// 16 warps, each a 32x32 output tile; K=128 in 8 steps. fp16 products are
// exact in fp32 -> dot error <= 9.8e-4 (pruning tolerance ERRB = 2.2e-3).
#define SMEM_WMMA (2*128*LDT*2)   // A + B fp16  (== 128*LDT*4 for D overlay)

__global__ void ls_wmma_kernel() {
    extern __shared__ __align__(16) char smem[];
    __half* sA = (__half*)smem;
    __half* sB = sA + 128*LDT;
    float*  sD = (float*)smem;                   // overlay after compute

    const int t   = threadIdx.x;                 // 512
    const int wid = t >> 5;
    const int i0  = blockIdx.y * LPB;
    const int j0  = blockIdx.x * LPB;

    {
        const __half* Ap = g_h1 + (size_t)(i0*NS)*DD;
        const __half* Bp = g_h2 + (size_t)(j0*NS)*DD;
        #pragma unroll
        for (int it = 0; it < 8; it++) {
            int e = t + it*512;                  // 125*32 = 4000 8B-chunks
            if (e < 125*32) {
                int row = e >> 5, c4 = (e & 31) * 4;
                *(unsigned long long*)&sA[row*LDT + c4] =
                    *(const unsigned long long*)(Ap + row*DD + c4);
                *(unsigned long long*)&sB[row*LDT + c4] =
                    *(const unsigned long long*)(Bp + row*DD + c4);
            }
        }
    }
    __syncthreads();

    const int wr = (wid >> 2) * 32;
    const int wc = (wid & 3) * 32;
    wmma::fragment<wmma::accumulator, 16, 16, 16, float> acc[2][2];
    #pragma unroll
    for (int i = 0; i < 2; i++)
        #pragma unroll
        for (int j = 0; j < 2; j++) wmma::fill_fragment(acc[i][j], 0.0f);

    #pragma unroll
    for (int k0 = 0; k0 < DD; k0 += 16) {
        wmma::fragment<wmma::matrix_a, 16, 16, 16, __half, wmma::row_major> af[2];
        wmma::fragment<wmma::matrix_b, 16, 16, 16, __half, wmma::col_major> bf[2];
        #pragma unroll
        for (int i = 0; i < 2; i++)
            wmma::load_matrix_sync(af[i], &sA[(wr + i*16)*LDT + k0], LDT);
        #pragma unroll
        for (int j = 0; j < 2; j++)
            wmma::load_matrix_sync(bf[j], &sB[(wc + j*16)*LDT + k0], LDT);
        #pragma unroll
        for (int i = 0; i < 2; i++)
            #pragma unroll
            for (int j = 0; j < 2; j++)
                wmma::mma_sync(acc[i][j], af[i], bf[j], acc[i][j]);
    }
    __syncthreads();                             // A/B dead; overlay D
    #pragma unroll
    for (int i = 0; i < 2; i++)
        #pragma unroll
        for (int j = 0; j < 2; j++)
            wmma::store_matrix_sync(&sD[(wr + i*16)*LDT + wc + j*16],
                                    acc[i][j], LDT, wmma::mem_row_major);
    __syncthreads();

    for (int p = t; p < LPB*LPB; p += 512) {
        int li = p / LPB, lj = p - li*LPB;
        int nsa = (int)g_ns[0][i0 + li];
        int nsb = (int)g_ns[1][j0 + lj];
        const float* base = &sD[(li*NS)*LDT + lj*NS];

        float ls1s = 0.0f, c1 = 0.0f;
        #pragma unroll
        for (int n = 0; n < 5; n++) {
            float mx = -3.0e38f;
            #pragma unroll
            for (int m = 0; m < 5; m++) {
                float sv = (n < nsa && m < nsb) ? base[n*LDT + m] : -1.0f;
                mx = fmaxf(mx, sv);
            }
            float v1 = (mx != -1.0f) ? 1.0f : 0.0f;
            ls1s = fa(ls1s, fm(mx, v1)); c1 = fa(c1, v1);
        }
        float ls2s = 0.0f, c2 = 0.0f;
        #pragma unroll
        for (int m = 0; m < 5; m++) {
            float mx = -3.0e38f;
            #pragma unroll
            for (int n = 0; n < 5; n++) {
                float sv = (n < nsa && m < nsb) ? base[n*LDT + m] : -1.0f;
                mx = fmaxf(mx, sv);
            }
            float v2 = (mx != -1.0f) ? 1.0f : 0.0f;
            ls2s = fa(ls2s, fm(mx, v2)); c2 = fa(c2, v2);
        }
        float lsc = __fdiv_rn(fa(__fdiv_rn(ls1s, c1), __fdiv_rn(ls2s, c2)), 2.0f);
        g_ls [(i0+li)*NL + (j0+lj)] = lsc;
        g_lsT[(j0+lj)*NL + (i0+li)] = lsc;
    }
}

// -------- kernel 3: approx top-10 -> exact rescue -> exact top-10 ------------
__global__ void topk_rescue_kernel() {
    __shared__ unsigned long long sred[256];
    __shared__ __align__(16) float sA2[5][132];
    __shared__ __align__(16) float sB2[8][5][132];
    __shared__ int s_cand[NCAND_MAX];
    __shared__ float s_cex[NCAND_MAX];
    __shared__ int s_cnt;
    __shared__ int s_woff[8];

    int row = blockIdx.x, dir = blockIdx.y;
    int t = threadIdx.x;                   // 256
    int wid = t >> 5, lane = t & 31;
    const float* ls = dir ? g_lsT : g_ls;

    // Phase 1: 10-pass approx top-10 -> 10th value
    unsigned long long prev = 0xFFFFFFFFFFFFFFFFull;
    for (int s = 0; s < TK; s++) {
        unsigned long long best = 0ull;
        for (int j = t; j < NL; j += 256) {
            unsigned long long key =
                ((unsigned long long)enc_f(ls[row*NL + j]) << 32) | (unsigned)j;
            if (key < prev && key > best) best = key;
        }
        sred[t] = best;
        __syncthreads();
        #pragma unroll
        for (int off = 128; off; off >>= 1) {
            if (t < off) { if (sred[t+off] > sred[t]) sred[t] = sred[t+off]; }
            __syncthreads();
        }
        prev = sred[0];
        __syncthreads();
    }
    float tau = fs(dec_f((unsigned)(prev >> 32)), ERRB);

    // Phase 2: ordered, deterministic candidate compaction (ascending j)
    if (t == 0) s_cnt = 0;
    __syncthreads();
    for (int j0 = 0; j0 < NL; j0 += 256) {
        int j = j0 + t;
        bool pred = (j < NL) && (ls[row*NL + j] >= tau);
        unsigned bal = __ballot_sync(0xffffffffu, pred);
        if (lane == 0) s_woff[wid] = __popc(bal);
        __syncthreads();
        if (t == 0) {
            int b = s_cnt;
            #pragma unroll
            for (int w = 0; w < 8; w++) { int c = s_woff[w]; s_woff[w] = b; b += c; }
            s_cnt = b;
        }
        __syncthreads();
        if (pred) {
            int pos = s_woff[wid] + __popc(bal & ((1u << lane) - 1u));
            if (pos < NCAND_MAX) s_cand[pos] = j;
        }
        __syncthreads();
    }
    int ncand = min(s_cnt, NCAND_MAX);

    // Phase 3: exact line scores for candidates (bit-identical arithmetic)
    const float* dA = dir ? g_d2 : g_d1;
    const float* dB = dir ? g_d1 : g_d2;
    int nsa = (int)g_ns[dir][row];
    if (t < 160) {
        int r = t >> 5, c4 = t & 31;
        *(float4*)&sA2[r][c4*4] = *(const float4*)&dA[(row*NS + r)*DD + c4*4];
    }
    int n = lane / 5, m = lane - n*5;
    for (int base = 0; base < ncand; base += 8) {
        #pragma unroll
        for (int i = 0; i < 8; i++) {
            if (base + i < ncand && t < 160) {
                int j = s_cand[base + i];
                int r = t >> 5, c4 = t & 31;
                *(float4*)&sB2[i][r][c4*4] = *(const float4*)&dB[(j*NS + r)*DD + c4*4];
            }
        }
        __syncthreads();
        int c = base + wid;
        if (c < ncand) {
            int j = s_cand[c];
            int nsb = (int)g_ns[1-dir][j];
            float acc = 0.0f;
            if (lane < 25) {
                const float4* ra = (const float4*)&sA2[n][0];
                const float4* rb = (const float4*)&sB2[wid][m][0];
                #pragma unroll 8
                for (int k4 = 0; k4 < DD/4; k4++) {
                    float4 a = ra[k4];
                    float4 b = rb[k4];
                    acc = __fmaf_rn(a.x, b.x, acc);
                    acc = __fmaf_rn(a.y, b.y, acc);
                    acc = __fmaf_rn(a.z, b.z, acc);
                    acc = __fmaf_rn(a.w, b.w, acc);
                }
            }
            float blk[25];
            #pragma unroll
            for (int i = 0; i < 25; i++)
                blk[i] = __shfl_sync(0xffffffffu, acc, i);
            if (lane == 0) {
                float ls1s = 0.0f, c1 = 0.0f;
                #pragma unroll
                for (int nn = 0; nn < 5; nn++) {
                    float mx = -3.0e38f;
                    #pragma unroll
                    for (int mm = 0; mm < 5; mm++) {
                        float sv = (nn < nsa && mm < nsb) ? blk[nn*5 + mm] : -1.0f;
                        mx = fmaxf(mx, sv);
                    }
                    float v1 = (mx != -1.0f) ? 1.0f : 0.0f;
                    ls1s = fa(ls1s, fm(mx, v1)); c1 = fa(c1, v1);
                }
                float ls2s = 0.0f, c2 = 0.0f;
                #pragma unroll
                for (int mm = 0; mm < 5; mm++) {
                    float mx = -3.0e38f;
                    #pragma unroll
                    for (int nn = 0; nn < 5; nn++) {
                        float sv = (nn < nsa && mm < nsb) ? blk[nn*5 + mm] : -1.0f;
                        mx = fmaxf(mx, sv);
                    }
                    float v2 = (mx != -1.0f) ? 1.0f : 0.0f;
                    ls2s = fa(ls2s, fm(mx, v2)); c2 = fa(c2, v2);
                }
                s_cex[c] = __fdiv_rn(fa(__fdiv_rn(ls1s, c1), __fdiv_rn(ls2s, c2)), 2.0f);
            }
        }
        __syncthreads();
    }

    // Phase 4: exact top-10 among candidates (same argsort-key semantics)
    if (wid == 0) {
        unsigned long long prv = 0xFFFFFFFFFFFFFFFFull;
        for (int s = 0; s < TK; s++) {
            unsigned long long best = 0ull;
            for (int c = lane; c < ncand; c += 32) {
                unsigned long long key =
                    ((unsigned long long)enc_f(s_cex[c]) << 32) | (unsigned)s_cand[c];
                if (key < prv && key > best) best = key;
            }
            #pragma unroll
            for (int off = 16; off; off >>= 1) {
                unsigned long long o = __shfl_xor_sync(0xffffffffu, best, off);
                if (o > best) best = o;
            }
            prv = best;
            if (lane == 0) g_topk[dir][row*TK + (TK-1-s)] = (int)(best & 0xFFFFFFFFull);
        }
    }
}

// ---------------- kernel 4: smem-staged 5x5 blocks + Needleman-Wunsch --------
__global__ void nw_kernel() {
    __shared__ __align__(16) float sA[5][132];
    __shared__ __align__(16) float sB[10][5][132];
    __shared__ int s_top[10];
    int line = blockIdx.x;
    int dir  = blockIdx.y;
    int t    = threadIdx.x;                 // 160

    const float* dA = dir ? g_d2 : g_d1;
    const float* dB = dir ? g_d1 : g_d2;

    if (t < 10) s_top[t] = g_topk[dir][line*TK + t];
    __syncthreads();

    {
        int r = t >> 5, c4 = t & 31;
        *(float4*)&sA[r][c4*4] = *(const float4*)&dA[(line*NS + r)*DD + c4*4];
    }
    #pragma unroll
    for (int i = 0; i < 10; i++) {
        int j = s_top[i];
        int r = t >> 5, c4 = t & 31;
        *(float4*)&sB[i][r][c4*4] = *(const float4*)&dB[(j*NS + r)*DD + c4*4];
    }
    __syncthreads();

    int warp = t >> 5, lane = t & 31;
    int na = (int)g_ns[dir][line];
    int n = lane / 5, m = lane - n*5;

    #pragma unroll
    for (int cc = 0; cc < 2; cc++) {
        int c = warp*2 + cc;
        int j = s_top[c];
        int nb = (int)g_ns[1-dir][j];

        float acc = 0.0f;
        if (lane < 25) {
            const float4* ra = (const float4*)&sA[n][0];
            const float4* rb = (const float4*)&sB[c][m][0];
            #pragma unroll 8
            for (int k4 = 0; k4 < DD/4; k4++) {
                float4 a = ra[k4];
                float4 b = rb[k4];
                acc = __fmaf_rn(a.x, b.x, acc);
                acc = __fmaf_rn(a.y, b.y, acc);
                acc = __fmaf_rn(a.z, b.z, acc);
                acc = __fmaf_rn(a.w, b.w, acc);
            }
        }
        float blk[25];
        #pragma unroll
        for (int i = 0; i < 25; i++)
            blk[i] = __shfl_sync(0xffffffffu, acc, i);

        if (lane < 2) {
            int flip = lane;
            float prev[6] = {0,0,0,0,0,0};
            #pragma unroll
            for (int r = 0; r < 5; r++) {
                float cur[6]; cur[0] = 0.0f;
                #pragma unroll
                for (int cI = 0; cI < 5; cI++) {
                    int sm = flip ? (4 - cI) : cI;
                    float sv = (r < na && sm < nb) ? blk[r*5 + sm] : -1.0f;
                    sv = fs(sv, GAPF);
                    cur[cI+1] = fmaxf(fmaxf(cur[cI], prev[cI+1]), fa(prev[cI], sv));
                }
                #pragma unroll
                for (int cI = 0; cI < 6; cI++) prev[cI] = cur[cI];
            }
            g_nw[dir][line*2*TK + flip*TK + c] = prev[5];
        }
    }
}

// ---------------- kernel 5: argmax over 20 candidates ------------------------
__global__ void argmax_kernel() {
    int idx = blockIdx.x * blockDim.x + threadIdx.x;
    if (idx >= 2*NL) return;
    int dir = idx / NL, line = idx - dir*NL;
    const float* nw = &g_nw[dir][line*2*TK];
    float best = nw[0]; int bi = 0;
    for (int t = 1; t < 2*TK; t++)
        if (nw[t] > best) { best = nw[t]; bi = t; }
    g_match[dir][line] = g_topk[dir][line*TK + (bi % TK)];
}

// ---------------- kernel 6: mutual check + write output ----------------------
__global__ void final_kernel(float* __restrict__ out, int out_size) {
    int idx = blockIdx.x * blockDim.x + threadIdx.x;
    if (idx >= NL + NL*2*TK || idx >= out_size) return;
    if (idx < NL) {
        int m  = g_match[0][idx];
        int ok = (g_match[1][m] == idx);
        out[idx] = ok ? (float)m : -1.0f;
    } else {
        out[idx] = g_nw[0][idx - NL];
    }
}

// ---------------- launcher ---------------------------------------------------
extern "C" void kernel_launch(void* const* d_in, const int* in_sizes, int n_in,
                              void* d_out, int out_size) {
    const float* seg1  = (const float*)d_in[0];
    const float* seg2  = (const float*)d_in[1];
    const float* desc1 = (const float*)d_in[2];
    const float* desc2 = (const float*)d_in[3];

    static int smem_set = 0;
    if (!smem_set) {
        cudaFuncSetAttribute(ls_wmma_kernel,
                             cudaFuncAttributeMaxDynamicSharedMemorySize, SMEM_WMMA);
        smem_set = 1;
    }

    {
        int warps = 2*NPTS;
        int threads = warps*32;
        sample_kernel<<<(threads + 255)/256, 256>>>(seg1, seg2, desc1, desc2);
    }
    ls_wmma_kernel<<<dim3(NL/LPB, NL/LPB), 512, SMEM_WMMA>>>();
    topk_rescue_kernel<<<dim3(NL, 2), 256>>>();
    nw_kernel<<<dim3(NL, 2), 160>>>();
    argmax_kernel<<<(2*NL + 255)/256, 256>>>();
    final_kernel<<<(NL + NL*2*TK + 255)/256, 256>>>((float*)d_out, out_size);
}

// round 15
// speedup vs baseline: 1.7898x; 1.0514x over previous
#include <cuda_runtime.h>
#include <cuda_fp16.h>
#include <mma.h>
#include <math.h>
#include <cstdint>

using namespace nvcuda;

#define NL   1200
#define NS   5
#define NPTS (NL*NS)      // 6000
#define DD   128
#define HH   128
#define WW   128
#define TK   10
#define GAPF 0.1f
#define NCAND_MAX 320
#define ERRB 0.0022f      // > 2 * fp16 dot error bound (2*9.8e-4)

#define LPB  25           // lines per tile side (25*5 = 125 rows of a 128 tile)
#define LDT  136          // smem leading dim, mult of 8

// ---------------- scratch (static __device__, no allocations) ----------------
static __device__ float g_d1[NPTS*DD];            // exact normalized descriptors
static __device__ float g_d2[NPTS*DD];
static __device__ __half g_h1[NPTS*DD];           // fp16 copies (same layout)
static __device__ __half g_h2[NPTS*DD];
static __device__ float g_ns[2][NL];
static __device__ float g_ls [NL*NL];             // APPROX line scores
static __device__ float g_lsT[NL*NL];
static __device__ int   g_topk[2][NL*TK];         // exact top-10, argsort order
static __device__ float g_nw [2][NL*2*TK];
static __device__ int   g_match[2][NL];

// Unfused helpers (match XLA's per-op rounding; no FMA contraction)
__device__ __forceinline__ float fm(float a, float b) { return __fmul_rn(a, b); }
__device__ __forceinline__ float fa(float a, float b) { return __fadd_rn(a, b); }
__device__ __forceinline__ float fs(float a, float b) { return __fsub_rn(a, b); }

// monotonic float<->uint for argsort-compatible keys
__device__ __forceinline__ unsigned enc_f(float v) {
    unsigned u = __float_as_uint(v);
    return (u & 0x80000000u) ? ~u : (u | 0x80000000u);
}
__device__ __forceinline__ float dec_f(unsigned u) {
    unsigned o = (u >> 31) ? (u & 0x7FFFFFFFu) : ~u;
    return __uint_as_float(o);
}

// ---------------- kernel 0: no-op (shifts ncu capture window to rescue) ------
__global__ void shift_kernel() {}

// ---------------- kernel 1: sample points + bilinear descriptors -------------
__device__ __forceinline__ float gat(const float* img, int x, int y) {
    if (x < 0 || x >= WW || y < 0 || y >= HH) return 0.0f;
    return img[y*WW + x];
}

__global__ void sample_kernel(const float* __restrict__ seg1,
                              const float* __restrict__ seg2,
                              const float* __restrict__ desc1,
                              const float* __restrict__ desc2) {
    int warp = (blockIdx.x * blockDim.x + threadIdx.x) >> 5;
    int lane = threadIdx.x & 31;
    if (warp >= 2*NPTS) return;
    int set  = warp / NPTS;
    int p    = warp - set*NPTS;
    int line = p / NS;
    int k    = p - line*NS;

    const float* seg  = set ? seg2  : seg1;
    const float* desc = set ? desc2 : desc1;
    float*       dout = set ? g_d2  : g_d1;
    __half*      hout = set ? g_h2  : g_h1;

    float sy = seg[line*4+0], sx = seg[line*4+1];
    float ey = seg[line*4+2], ex = seg[line*4+3];
    float dy = fs(ey, sy), dx = fs(ex, sx);
    float len = sqrtf(fa(fm(dy, dy), fm(dx, dx)));
    float ns  = fminf(fmaxf(floorf(__fdiv_rn(len, 8.0f)), 2.0f), 5.0f);
    if (k == 0 && lane == 0) g_ns[set][line] = ns;

    float nm1 = fs(ns, 1.0f);
    float ivy = __fdiv_rn(dy, nm1);
    float ivx = __fdiv_rn(dx, nm1);
    float kf  = (float)k;
    float py  = fa(sy, fm(kf, ivy));
    float px  = fa(sx, fm(kf, ivx));
    if (!(kf < ns)) { py = 0.0f; px = 0.0f; }

    float xn  = fs(__fdiv_rn(fm(2.0f, px), (float)(WW*4 - 1)), 1.0f);
    float yn  = fs(__fdiv_rn(fm(2.0f, py), (float)(HH*4 - 1)), 1.0f);
    float ixf = __fdiv_rn(fs(fm(fa(xn, 1.0f), (float)WW), 1.0f), 2.0f);
    float iyf = __fdiv_rn(fs(fm(fa(yn, 1.0f), (float)HH), 1.0f), 2.0f);
    float x0f = floorf(ixf), y0f = floorf(iyf);
    float wx = fs(ixf, x0f), wy = fs(iyf, y0f);
    int   x0 = (int)x0f,  y0 = (int)y0f;
    float w00 = fm(fs(1.0f, wx), fs(1.0f, wy));
    float w10 = fm(wx, fs(1.0f, wy));
    float w01 = fm(fs(1.0f, wx), wy);
    float w11 = fm(wx, wy);

    float v[4];
    float ss = 0.0f;
    #pragma unroll
    for (int q = 0; q < 4; q++) {
        int d = lane + q*32;
        const float* img = desc + d*HH*WW;
        float a = fm(gat(img, x0,   y0  ), w00);
        a = fa(a, fm(gat(img, x0+1, y0  ), w10));
        a = fa(a, fm(gat(img, x0,   y0+1), w01));
        a = fa(a, fm(gat(img, x0+1, y0+1), w11));
        v[q] = a;
        ss = fa(ss, fm(a, a));
    }
    #pragma unroll
    for (int off = 16; off; off >>= 1)
        ss = fa(ss, __shfl_xor_sync(0xffffffffu, ss, off));
    float nrm = sqrtf(ss);
    #pragma unroll
    for (int q = 0; q < 4; q++) {
        float val = __fdiv_rn(v[q], nrm);
        dout[p*DD + lane + q*32] = val;
        hout[p*DD + lane + q*32] = __float2half(val);
    }
}

// ------------- kernel 2: wmma fp16 GEMM -> APPROX line scores ----------------
#define SMEM_WMMA (2*128*LDT*2)   // A + B fp16  (== 128*LDT*4 for D overlay)

__global__ void ls_wmma_kernel() {
    extern __shared__ __align__(16) char smem[];
    __half* sA = (__half*)smem;
    __half* sB = sA + 128*LDT;
    float*  sD = (float*)smem;                   // overlay after compute

    const int t   = threadIdx.x;                 // 512
    const int wid = t >> 5;
    const int i0  = blockIdx.y * LPB;
    const int j0  = blockIdx.x * LPB;

    {
        const __half* Ap = g_h1 + (size_t)(i0*NS)*DD;
        const __half* Bp = g_h2 + (size_t)(j0*NS)*DD;
        #pragma unroll
        for (int it = 0; it < 8; it++) {
            int e = t + it*512;                  // 125*32 = 4000 8B-chunks
            if (e < 125*32) {
                int row = e >> 5, c4 = (e & 31) * 4;
                *(unsigned long long*)&sA[row*LDT + c4] =
                    *(const unsigned long long*)(Ap + row*DD + c4);
                *(unsigned long long*)&sB[row*LDT + c4] =
                    *(const unsigned long long*)(Bp + row*DD + c4);
            }
        }
    }
    __syncthreads();

    const int wr = (wid >> 2) * 32;
    const int wc = (wid & 3) * 32;
    wmma::fragment<wmma::accumulator, 16, 16, 16, float> acc[2][2];
    #pragma unroll
    for (int i = 0; i < 2; i++)
        #pragma unroll
        for (int j = 0; j < 2; j++) wmma::fill_fragment(acc[i][j], 0.0f);

    #pragma unroll
    for (int k0 = 0; k0 < DD; k0 += 16) {
        wmma::fragment<wmma::matrix_a, 16, 16, 16, __half, wmma::row_major> af[2];
        wmma::fragment<wmma::matrix_b, 16, 16, 16, __half, wmma::col_major> bf[2];
        #pragma unroll
        for (int i = 0; i < 2; i++)
            wmma::load_matrix_sync(af[i], &sA[(wr + i*16)*LDT + k0], LDT);
        #pragma unroll
        for (int j = 0; j < 2; j++)
            wmma::load_matrix_sync(bf[j], &sB[(wc + j*16)*LDT + k0], LDT);
        #pragma unroll
        for (int i = 0; i < 2; i++)
            #pragma unroll
            for (int j = 0; j < 2; j++)
                wmma::mma_sync(acc[i][j], af[i], bf[j], acc[i][j]);
    }
    __syncthreads();                             // A/B dead; overlay D
    #pragma unroll
    for (int i = 0; i < 2; i++)
        #pragma unroll
        for (int j = 0; j < 2; j++)
            wmma::store_matrix_sync(&sD[(wr + i*16)*LDT + wc + j*16],
                                    acc[i][j], LDT, wmma::mem_row_major);
    __syncthreads();

    for (int p = t; p < LPB*LPB; p += 512) {
        int li = p / LPB, lj = p - li*LPB;
        int nsa = (int)g_ns[0][i0 + li];
        int nsb = (int)g_ns[1][j0 + lj];
        const float* base = &sD[(li*NS)*LDT + lj*NS];

        float ls1s = 0.0f, c1 = 0.0f;
        #pragma unroll
        for (int n = 0; n < 5; n++) {
            float mx = -3.0e38f;
            #pragma unroll
            for (int m = 0; m < 5; m++) {
                float sv = (n < nsa && m < nsb) ? base[n*LDT + m] : -1.0f;
                mx = fmaxf(mx, sv);
            }
            float v1 = (mx != -1.0f) ? 1.0f : 0.0f;
            ls1s = fa(ls1s, fm(mx, v1)); c1 = fa(c1, v1);
        }
        float ls2s = 0.0f, c2 = 0.0f;
        #pragma unroll
        for (int m = 0; m < 5; m++) {
            float mx = -3.0e38f;
            #pragma unroll
            for (int n = 0; n < 5; n++) {
                float sv = (n < nsa && m < nsb) ? base[n*LDT + m] : -1.0f;
                mx = fmaxf(mx, sv);
            }
            float v2 = (mx != -1.0f) ? 1.0f : 0.0f;
            ls2s = fa(ls2s, fm(mx, v2)); c2 = fa(c2, v2);
        }
        float lsc = __fdiv_rn(fa(__fdiv_rn(ls1s, c1), __fdiv_rn(ls2s, c2)), 2.0f);
        g_ls [(i0+li)*NL + (j0+lj)] = lsc;
        g_lsT[(j0+lj)*NL + (i0+li)] = lsc;
    }
}

// -------- kernel 3: approx top-10 -> exact rescue -> exact top-10 ------------
__global__ void topk_rescue_kernel() {
    __shared__ unsigned long long sred[256];
    __shared__ __align__(16) float sA2[5][132];
    __shared__ __align__(16) float sB2[8][5][132];
    __shared__ int s_cand[NCAND_MAX];
    __shared__ float s_cex[NCAND_MAX];
    __shared__ int s_cnt;
    __shared__ int s_woff[8];

    int row = blockIdx.x, dir = blockIdx.y;
    int t = threadIdx.x;                   // 256
    int wid = t >> 5, lane = t & 31;
    const float* ls = dir ? g_lsT : g_ls;

    // Phase 1: 10-pass approx top-10 -> 10th value
    unsigned long long prev = 0xFFFFFFFFFFFFFFFFull;
    for (int s = 0; s < TK; s++) {
        unsigned long long best = 0ull;
        for (int j = t; j < NL; j += 256) {
            unsigned long long key =
                ((unsigned long long)enc_f(ls[row*NL + j]) << 32) | (unsigned)j;
            if (key < prev && key > best) best = key;
        }
        sred[t] = best;
        __syncthreads();
        #pragma unroll
        for (int off = 128; off; off >>= 1) {
            if (t < off) { if (sred[t+off] > sred[t]) sred[t] = sred[t+off]; }
            __syncthreads();
        }
        prev = sred[0];
        __syncthreads();
    }
    float tau = fs(dec_f((unsigned)(prev >> 32)), ERRB);

    // Phase 2: ordered, deterministic candidate compaction (ascending j)
    if (t == 0) s_cnt = 0;
    __syncthreads();
    for (int j0 = 0; j0 < NL; j0 += 256) {
        int j = j0 + t;
        bool pred = (j < NL) && (ls[row*NL + j] >= tau);
        unsigned bal = __ballot_sync(0xffffffffu, pred);
        if (lane == 0) s_woff[wid] = __popc(bal);
        __syncthreads();
        if (t == 0) {
            int b = s_cnt;
            #pragma unroll
            for (int w = 0; w < 8; w++) { int c = s_woff[w]; s_woff[w] = b; b += c; }
            s_cnt = b;
        }
        __syncthreads();
        if (pred) {
            int pos = s_woff[wid] + __popc(bal & ((1u << lane) - 1u));
            if (pos < NCAND_MAX) s_cand[pos] = j;
        }
        __syncthreads();
    }
    int ncand = min(s_cnt, NCAND_MAX);

    // Phase 3: exact line scores for candidates (bit-identical arithmetic)
    const float* dA = dir ? g_d2 : g_d1;
    const float* dB = dir ? g_d1 : g_d2;
    int nsa = (int)g_ns[dir][row];
    if (t < 160) {
        int r = t >> 5, c4 = t & 31;
        *(float4*)&sA2[r][c4*4] = *(const float4*)&dA[(row*NS + r)*DD + c4*4];
    }
    int n = lane / 5, m = lane - n*5;
    for (int base = 0; base < ncand; base += 8) {
        #pragma unroll
        for (int i = 0; i < 8; i++) {
            if (base + i < ncand && t < 160) {
                int j = s_cand[base + i];
                int r = t >> 5, c4 = t & 31;
                *(float4*)&sB2[i][r][c4*4] = *(const float4*)&dB[(j*NS + r)*DD + c4*4];
            }
        }
        __syncthreads();
        int c = base + wid;
        if (c < ncand) {
            int j = s_cand[c];
            int nsb = (int)g_ns[1-dir][j];
            float acc = 0.0f;
            if (lane < 25) {
                const float4* ra = (const float4*)&sA2[n][0];
                const float4* rb = (const float4*)&sB2[wid][m][0];
                #pragma unroll 8
                for (int k4 = 0; k4 < DD/4; k4++) {
                    float4 a = ra[k4];
                    float4 b = rb[k4];
                    acc = __fmaf_rn(a.x, b.x, acc);
                    acc = __fmaf_rn(a.y, b.y, acc);
                    acc = __fmaf_rn(a.z, b.z, acc);
                    acc = __fmaf_rn(a.w, b.w, acc);
                }
            }
            float blk[25];
            #pragma unroll
            for (int i = 0; i < 25; i++)
                blk[i] = __shfl_sync(0xffffffffu, acc, i);
            if (lane == 0) {
                float ls1s = 0.0f, c1 = 0.0f;
                #pragma unroll
                for (int nn = 0; nn < 5; nn++) {
                    float mx = -3.0e38f;
                    #pragma unroll
                    for (int mm = 0; mm < 5; mm++) {
                        float sv = (nn < nsa && mm < nsb) ? blk[nn*5 + mm] : -1.0f;
                        mx = fmaxf(mx, sv);
                    }
                    float v1 = (mx != -1.0f) ? 1.0f : 0.0f;
                    ls1s = fa(ls1s, fm(mx, v1)); c1 = fa(c1, v1);
                }
                float ls2s = 0.0f, c2 = 0.0f;
                #pragma unroll
                for (int mm = 0; mm < 5; mm++) {
                    float mx = -3.0e38f;
                    #pragma unroll
                    for (int nn = 0; nn < 5; nn++) {
                        float sv = (nn < nsa && mm < nsb) ? blk[nn*5 + mm] : -1.0f;
                        mx = fmaxf(mx, sv);
                    }
                    float v2 = (mx != -1.0f) ? 1.0f : 0.0f;
                    ls2s = fa(ls2s, fm(mx, v2)); c2 = fa(c2, v2);
                }
                s_cex[c] = __fdiv_rn(fa(__fdiv_rn(ls1s, c1), __fdiv_rn(ls2s, c2)), 2.0f);
            }
        }
        __syncthreads();
    }

    // Phase 4: exact top-10 among candidates (same argsort-key semantics)
    if (wid == 0) {
        unsigned long long prv = 0xFFFFFFFFFFFFFFFFull;
        for (int s = 0; s < TK; s++) {
            unsigned long long best = 0ull;
            for (int c = lane; c < ncand; c += 32) {
                unsigned long long key =
                    ((unsigned long long)enc_f(s_cex[c]) << 32) | (unsigned)s_cand[c];
                if (key < prv && key > best) best = key;
            }
            #pragma unroll
            for (int off = 16; off; off >>= 1) {
                unsigned long long o = __shfl_xor_sync(0xffffffffu, best, off);
                if (o > best) best = o;
            }
            prv = best;
            if (lane == 0) g_topk[dir][row*TK + (TK-1-s)] = (int)(best & 0xFFFFFFFFull);
        }
    }
}

// -------- kernel 4: NW (interleaved 2-cand chains) + fused argmax ------------
__global__ void nw_kernel() {
    __shared__ __align__(16) float sA[5][132];
    __shared__ __align__(16) float sB[10][5][132];
    __shared__ float s_blk[10][26];
    __shared__ int s_top[10];
    __shared__ float s_nw[2*TK];
    int line = blockIdx.x;
    int dir  = blockIdx.y;
    int t    = threadIdx.x;                 // 160

    const float* dA = dir ? g_d2 : g_d1;
    const float* dB = dir ? g_d1 : g_d2;

    if (t < 10) s_top[t] = g_topk[dir][line*TK + t];
    __syncthreads();

    {
        int r = t >> 5, c4 = t & 31;
        *(float4*)&sA[r][c4*4] = *(const float4*)&dA[(line*NS + r)*DD + c4*4];
    }
    #pragma unroll
    for (int i = 0; i < 10; i++) {
        int j = s_top[i];
        int r = t >> 5, c4 = t & 31;
        *(float4*)&sB[i][r][c4*4] = *(const float4*)&dB[(j*NS + r)*DD + c4*4];
    }
    __syncthreads();

    int warp = t >> 5, lane = t & 31;
    int na = (int)g_ns[dir][line];
    int n = lane / 5, m = lane - n*5;
    int c0 = warp*2, c1 = warp*2 + 1;

    // Two independent serial chains per lane (each still sequential x,y,z,w
    // in k-order -> per-dot arithmetic bit-identical to the 215.8us kernel).
    float acc0 = 0.0f, acc1 = 0.0f;
    if (lane < 25) {
        const float4* ra  = (const float4*)&sA[n][0];
        const float4* rb0 = (const float4*)&sB[c0][m][0];
        const float4* rb1 = (const float4*)&sB[c1][m][0];
        #pragma unroll 8
        for (int k4 = 0; k4 < DD/4; k4++) {
            float4 a = ra[k4];
            float4 b0 = rb0[k4];
            float4 b1 = rb1[k4];
            acc0 = __fmaf_rn(a.x, b0.x, acc0);
            acc0 = __fmaf_rn(a.y, b0.y, acc0);
            acc0 = __fmaf_rn(a.z, b0.z, acc0);
            acc0 = __fmaf_rn(a.w, b0.w, acc0);
            acc1 = __fmaf_rn(a.x, b1.x, acc1);
            acc1 = __fmaf_rn(a.y, b1.y, acc1);
            acc1 = __fmaf_rn(a.z, b1.z, acc1);
            acc1 = __fmaf_rn(a.w, b1.w, acc1);
        }
        s_blk[c0][lane] = acc0;
        s_blk[c1][lane] = acc1;
    }
    __syncwarp();

    // lanes 0..3: candidate = c0/c1 (lane>>1), flip = lane&1; dots from smem
    if (lane < 4) {
        int c    = (lane >> 1) ? c1 : c0;
        int flip = lane & 1;
        int j = s_top[c];
        int nb = (int)g_ns[1-dir][j];
        const float* blk = &s_blk[c][0];
        float prev[6] = {0,0,0,0,0,0};
        #pragma unroll
        for (int r = 0; r < 5; r++) {
            float cur[6]; cur[0] = 0.0f;
            #pragma unroll
            for (int cI = 0; cI < 5; cI++) {
                int sm = flip ? (4 - cI) : cI;
                float sv = (r < na && sm < nb) ? blk[r*5 + sm] : -1.0f;
                sv = fs(sv, GAPF);
                cur[cI+1] = fmaxf(fmaxf(cur[cI], prev[cI+1]), fa(prev[cI], sv));
            }
            #pragma unroll
            for (int cI = 0; cI < 6; cI++) prev[cI] = cur[cI];
        }
        g_nw[dir][line*2*TK + flip*TK + c] = prev[5];
        s_nw[flip*TK + c] = prev[5];
    }
    __syncthreads();

    // fused argmax (first-occurrence over t = flip*TK + c, same as reference)
    if (t == 0) {
        float best = s_nw[0]; int bi = 0;
        for (int q = 1; q < 2*TK; q++)
            if (s_nw[q] > best) { best = s_nw[q]; bi = q; }
        g_match[dir][line] = s_top[bi % TK];
    }
}

// ---------------- kernel 5: mutual check + write output ----------------------
__global__ void final_kernel(float* __restrict__ out, int out_size) {
    int idx = blockIdx.x * blockDim.x + threadIdx.x;
    if (idx >= NL + NL*2*TK || idx >= out_size) return;
    if (idx < NL) {
        int m  = g_match[0][idx];
        int ok = (g_match[1][m] == idx);
        out[idx] = ok ? (float)m : -1.0f;
    } else {
        out[idx] = g_nw[0][idx - NL];
    }
}

// ---------------- launcher ---------------------------------------------------
extern "C" void kernel_launch(void* const* d_in, const int* in_sizes, int n_in,
                              void* d_out, int out_size) {
    const float* seg1  = (const float*)d_in[0];
    const float* seg2  = (const float*)d_in[1];
    const float* desc1 = (const float*)d_in[2];
    const float* desc2 = (const float*)d_in[3];

    static int smem_set = 0;
    if (!smem_set) {
        cudaFuncSetAttribute(ls_wmma_kernel,
                             cudaFuncAttributeMaxDynamicSharedMemorySize, SMEM_WMMA);
        smem_set = 1;
    }

    shift_kernel<<<1, 32>>>();   // shifts ncu -s window onto topk_rescue_kernel
    {
        int warps = 2*NPTS;
        int threads = warps*32;
        sample_kernel<<<(threads + 255)/256, 256>>>(seg1, seg2, desc1, desc2);
    }
    ls_wmma_kernel<<<dim3(NL/LPB, NL/LPB), 512, SMEM_WMMA>>>();
    topk_rescue_kernel<<<dim3(NL, 2), 256>>>();
    nw_kernel<<<dim3(NL, 2), 160>>>();
    final_kernel<<<(NL + NL*2*TK + 255)/256, 256>>>((float*)d_out, out_size);
}

// round 16
// speedup vs baseline: 1.8421x; 1.0292x over previous
#include <cuda_runtime.h>
#include <cuda_fp16.h>
#include <mma.h>
#include <math.h>
#include <cstdint>

using namespace nvcuda;

#define NL   1200
#define NS   5
#define NPTS (NL*NS)      // 6000
#define DD   128
#define HH   128
#define WW   128
#define TK   10
#define GAPF 0.1f
#define NCAND_MAX 320
#define ERRB 0.0022f      // > 2 * fp16 dot error bound (2*9.8e-4)

#define LPB  25           // lines per tile side (25*5 = 125 rows of a 128 tile)
#define LDT  136          // smem leading dim, mult of 8

// ---------------- scratch (static __device__, no allocations) ----------------
static __device__ float g_d1[NPTS*DD];            // exact normalized descriptors
static __device__ float g_d2[NPTS*DD];
static __device__ __half g_h1[NPTS*DD];           // fp16 copies (same layout)
static __device__ __half g_h2[NPTS*DD];
static __device__ float g_ns[2][NL];
static __device__ float g_ls [NL*NL];             // APPROX line scores
static __device__ float g_lsT[NL*NL];
static __device__ int   g_topk[2][NL*TK];         // exact top-10, argsort order
static __device__ float g_nw [2][NL*2*TK];
static __device__ int   g_match[2][NL];

// Unfused helpers (match XLA's per-op rounding; no FMA contraction)
__device__ __forceinline__ float fm(float a, float b) { return __fmul_rn(a, b); }
__device__ __forceinline__ float fa(float a, float b) { return __fadd_rn(a, b); }
__device__ __forceinline__ float fs(float a, float b) { return __fsub_rn(a, b); }

// monotonic float<->uint for argsort-compatible keys
__device__ __forceinline__ unsigned enc_f(float v) {
    unsigned u = __float_as_uint(v);
    return (u & 0x80000000u) ? ~u : (u | 0x80000000u);
}
__device__ __forceinline__ float dec_f(unsigned u) {
    unsigned o = (u >> 31) ? (u & 0x7FFFFFFFu) : ~u;
    return __uint_as_float(o);
}

// ---------------- kernel 0: no-op (shifts ncu capture window to rescue) ------
__global__ void shift_kernel() {}

// ---------------- kernel 1: sample points + bilinear descriptors -------------
__device__ __forceinline__ float gat(const float* img, int x, int y) {
    if (x < 0 || x >= WW || y < 0 || y >= HH) return 0.0f;
    return img[y*WW + x];
}

__global__ void sample_kernel(const float* __restrict__ seg1,
                              const float* __restrict__ seg2,
                              const float* __restrict__ desc1,
                              const float* __restrict__ desc2) {
    int warp = (blockIdx.x * blockDim.x + threadIdx.x) >> 5;
    int lane = threadIdx.x & 31;
    if (warp >= 2*NPTS) return;
    int set  = warp / NPTS;
    int p    = warp - set*NPTS;
    int line = p / NS;
    int k    = p - line*NS;

    const float* seg  = set ? seg2  : seg1;
    const float* desc = set ? desc2 : desc1;
    float*       dout = set ? g_d2  : g_d1;
    __half*      hout = set ? g_h2  : g_h1;

    float sy = seg[line*4+0], sx = seg[line*4+1];
    float ey = seg[line*4+2], ex = seg[line*4+3];
    float dy = fs(ey, sy), dx = fs(ex, sx);
    float len = sqrtf(fa(fm(dy, dy), fm(dx, dx)));
    float ns  = fminf(fmaxf(floorf(__fdiv_rn(len, 8.0f)), 2.0f), 5.0f);
    if (k == 0 && lane == 0) g_ns[set][line] = ns;

    float nm1 = fs(ns, 1.0f);
    float ivy = __fdiv_rn(dy, nm1);
    float ivx = __fdiv_rn(dx, nm1);
    float kf  = (float)k;
    float py  = fa(sy, fm(kf, ivy));
    float px  = fa(sx, fm(kf, ivx));
    if (!(kf < ns)) { py = 0.0f; px = 0.0f; }

    float xn  = fs(__fdiv_rn(fm(2.0f, px), (float)(WW*4 - 1)), 1.0f);
    float yn  = fs(__fdiv_rn(fm(2.0f, py), (float)(HH*4 - 1)), 1.0f);
    float ixf = __fdiv_rn(fs(fm(fa(xn, 1.0f), (float)WW), 1.0f), 2.0f);
    float iyf = __fdiv_rn(fs(fm(fa(yn, 1.0f), (float)HH), 1.0f), 2.0f);
    float x0f = floorf(ixf), y0f = floorf(iyf);
    float wx = fs(ixf, x0f), wy = fs(iyf, y0f);
    int   x0 = (int)x0f,  y0 = (int)y0f;
    float w00 = fm(fs(1.0f, wx), fs(1.0f, wy));
    float w10 = fm(wx, fs(1.0f, wy));
    float w01 = fm(fs(1.0f, wx), wy);
    float w11 = fm(wx, wy);

    float v[4];
    float ss = 0.0f;
    #pragma unroll
    for (int q = 0; q < 4; q++) {
        int d = lane + q*32;
        const float* img = desc + d*HH*WW;
        float a = fm(gat(img, x0,   y0  ), w00);
        a = fa(a, fm(gat(img, x0+1, y0  ), w10));
        a = fa(a, fm(gat(img, x0,   y0+1), w01));
        a = fa(a, fm(gat(img, x0+1, y0+1), w11));
        v[q] = a;
        ss = fa(ss, fm(a, a));
    }
    #pragma unroll
    for (int off = 16; off; off >>= 1)
        ss = fa(ss, __shfl_xor_sync(0xffffffffu, ss, off));
    float nrm = sqrtf(ss);
    #pragma unroll
    for (int q = 0; q < 4; q++) {
        float val = __fdiv_rn(v[q], nrm);
        dout[p*DD + lane + q*32] = val;
        hout[p*DD + lane + q*32] = __float2half(val);
    }
}

// ------------- kernel 2: wmma fp16 GEMM -> APPROX line scores ----------------
#define SMEM_WMMA (2*128*LDT*2)   // A + B fp16  (== 128*LDT*4 for D overlay)

__global__ void ls_wmma_kernel() {
    extern __shared__ __align__(16) char smem[];
    __half* sA = (__half*)smem;
    __half* sB = sA + 128*LDT;
    float*  sD = (float*)smem;                   // overlay after compute

    const int t   = threadIdx.x;                 // 512
    const int wid = t >> 5;
    const int i0  = blockIdx.y * LPB;
    const int j0  = blockIdx.x * LPB;

    {
        const __half* Ap = g_h1 + (size_t)(i0*NS)*DD;
        const __half* Bp = g_h2 + (size_t)(j0*NS)*DD;
        #pragma unroll
        for (int it = 0; it < 8; it++) {
            int e = t + it*512;                  // 125*32 = 4000 8B-chunks
            if (e < 125*32) {
                int row = e >> 5, c4 = (e & 31) * 4;
                *(unsigned long long*)&sA[row*LDT + c4] =
                    *(const unsigned long long*)(Ap + row*DD + c4);
                *(unsigned long long*)&sB[row*LDT + c4] =
                    *(const unsigned long long*)(Bp + row*DD + c4);
            }
        }
    }
    __syncthreads();

    const int wr = (wid >> 2) * 32;
    const int wc = (wid & 3) * 32;
    wmma::fragment<wmma::accumulator, 16, 16, 16, float> acc[2][2];
    #pragma unroll
    for (int i = 0; i < 2; i++)
        #pragma unroll
        for (int j = 0; j < 2; j++) wmma::fill_fragment(acc[i][j], 0.0f);

    #pragma unroll
    for (int k0 = 0; k0 < DD; k0 += 16) {
        wmma::fragment<wmma::matrix_a, 16, 16, 16, __half, wmma::row_major> af[2];
        wmma::fragment<wmma::matrix_b, 16, 16, 16, __half, wmma::col_major> bf[2];
        #pragma unroll
        for (int i = 0; i < 2; i++)
            wmma::load_matrix_sync(af[i], &sA[(wr + i*16)*LDT + k0], LDT);
        #pragma unroll
        for (int j = 0; j < 2; j++)
            wmma::load_matrix_sync(bf[j], &sB[(wc + j*16)*LDT + k0], LDT);
        #pragma unroll
        for (int i = 0; i < 2; i++)
            #pragma unroll
            for (int j = 0; j < 2; j++)
                wmma::mma_sync(acc[i][j], af[i], bf[j], acc[i][j]);
    }
    __syncthreads();                             // A/B dead; overlay D
    #pragma unroll
    for (int i = 0; i < 2; i++)
        #pragma unroll
        for (int j = 0; j < 2; j++)
            wmma::store_matrix_sync(&sD[(wr + i*16)*LDT + wc + j*16],
                                    acc[i][j], LDT, wmma::mem_row_major);
    __syncthreads();

    for (int p = t; p < LPB*LPB; p += 512) {
        int li = p / LPB, lj = p - li*LPB;
        int nsa = (int)g_ns[0][i0 + li];
        int nsb = (int)g_ns[1][j0 + lj];
        const float* base = &sD[(li*NS)*LDT + lj*NS];

        float ls1s = 0.0f, c1 = 0.0f;
        #pragma unroll
        for (int n = 0; n < 5; n++) {
            float mx = -3.0e38f;
            #pragma unroll
            for (int m = 0; m < 5; m++) {
                float sv = (n < nsa && m < nsb) ? base[n*LDT + m] : -1.0f;
                mx = fmaxf(mx, sv);
            }
            float v1 = (mx != -1.0f) ? 1.0f : 0.0f;
            ls1s = fa(ls1s, fm(mx, v1)); c1 = fa(c1, v1);
        }
        float ls2s = 0.0f, c2 = 0.0f;
        #pragma unroll
        for (int m = 0; m < 5; m++) {
            float mx = -3.0e38f;
            #pragma unroll
            for (int n = 0; n < 5; n++) {
                float sv = (n < nsa && m < nsb) ? base[n*LDT + m] : -1.0f;
                mx = fmaxf(mx, sv);
            }
            float v2 = (mx != -1.0f) ? 1.0f : 0.0f;
            ls2s = fa(ls2s, fm(mx, v2)); c2 = fa(c2, v2);
        }
        float lsc = __fdiv_rn(fa(__fdiv_rn(ls1s, c1), __fdiv_rn(ls2s, c2)), 2.0f);
        g_ls [(i0+li)*NL + (j0+lj)] = lsc;
        g_lsT[(j0+lj)*NL + (i0+li)] = lsc;
    }
}

// -------- kernel 3: approx top-10 -> exact rescue -> exact top-10 ------------
// Phase 1: register-resident keys + shfl reduce. Phase 3: 16 tiles/iter,
// dual-candidate interleaved chains per warp (bit-identical per-dot order).
__global__ void topk_rescue_kernel() {
    __shared__ unsigned long long sred[8];
    __shared__ unsigned long long s_prev;
    __shared__ __align__(16) float sA2[5][132];
    __shared__ __align__(16) float sB2[16][5][132];
    __shared__ int s_cand[NCAND_MAX];
    __shared__ float s_cex[NCAND_MAX];
    __shared__ int s_cnt;
    __shared__ int s_woff[8];

    int row = blockIdx.x, dir = blockIdx.y;
    int t = threadIdx.x;                   // 256
    int wid = t >> 5, lane = t & 31;
    const float* ls = dir ? g_lsT : g_ls;

    // Phase 1: load this thread's <=5 keys once, then 10 register-scan passes.
    unsigned long long mykey[5];
    #pragma unroll
    for (int i = 0; i < 5; i++) {
        int j = t + i*256;
        mykey[i] = (j < NL)
            ? (((unsigned long long)enc_f(ls[row*NL + j]) << 32) | (unsigned)j)
            : 0ull;
    }
    unsigned long long prev = 0xFFFFFFFFFFFFFFFFull;
    for (int s = 0; s < TK; s++) {
        unsigned long long best = 0ull;
        #pragma unroll
        for (int i = 0; i < 5; i++)
            if (mykey[i] < prev && mykey[i] > best) best = mykey[i];
        #pragma unroll
        for (int off = 16; off; off >>= 1) {
            unsigned long long o = __shfl_xor_sync(0xffffffffu, best, off);
            if (o > best) best = o;
        }
        if (lane == 0) sred[wid] = best;
        __syncthreads();
        if (t == 0) {
            unsigned long long b = sred[0];
            #pragma unroll
            for (int w = 1; w < 8; w++) if (sred[w] > b) b = sred[w];
            s_prev = b;
        }
        __syncthreads();
        prev = s_prev;
    }
    float tau = fs(dec_f((unsigned)(prev >> 32)), ERRB);

    // Phase 2: ordered, deterministic candidate compaction (ascending j)
    if (t == 0) s_cnt = 0;
    __syncthreads();
    for (int j0 = 0; j0 < NL; j0 += 256) {
        int j = j0 + t;
        bool pred = (j < NL) && (ls[row*NL + j] >= tau);
        unsigned bal = __ballot_sync(0xffffffffu, pred);
        if (lane == 0) s_woff[wid] = __popc(bal);
        __syncthreads();
        if (t == 0) {
            int b = s_cnt;
            #pragma unroll
            for (int w = 0; w < 8; w++) { int c = s_woff[w]; s_woff[w] = b; b += c; }
            s_cnt = b;
        }
        __syncthreads();
        if (pred) {
            int pos = s_woff[wid] + __popc(bal & ((1u << lane) - 1u));
            if (pos < NCAND_MAX) s_cand[pos] = j;
        }
        __syncthreads();
    }
    int ncand = min(s_cnt, NCAND_MAX);

    // Phase 3: exact line scores; 16 candidates per iteration, 2 per warp with
    // interleaved serial chains (per-dot k-order identical to before).
    const float* dA = dir ? g_d2 : g_d1;
    const float* dB = dir ? g_d1 : g_d2;
    int nsa = (int)g_ns[dir][row];
    if (t < 160) {
        int r = t >> 5, c4 = t & 31;
        *(float4*)&sA2[r][c4*4] = *(const float4*)&dA[(row*NS + r)*DD + c4*4];
    }
    int n = lane / 5, m = lane - n*5;
    for (int base = 0; base < ncand; base += 16) {
        // load up to 16 tiles: 2560 float4 chunks / 256 threads = 10 each
        #pragma unroll
        for (int it = 0; it < 10; it++) {
            int e = t + it*256;
            int tile = e / 160;
            int q = e - tile*160;
            int r = q >> 5, c4 = q & 31;
            if (base + tile < ncand) {
                int j = s_cand[base + tile];
                *(float4*)&sB2[tile][r][c4*4] =
                    *(const float4*)&dB[(j*NS + r)*DD + c4*4];
            }
        }
        __syncthreads();
        int cA = base + wid;
        int cB = base + wid + 8;
        bool hasA = (cA < ncand), hasB = (cB < ncand);
        float acc0 = 0.0f, acc1 = 0.0f;
        if (lane < 25) {
            const float4* ra  = (const float4*)&sA2[n][0];
            const float4* rb0 = (const float4*)&sB2[wid][m][0];
            const float4* rb1 = (const float4*)&sB2[wid + 8][m][0];
            #pragma unroll 8
            for (int k4 = 0; k4 < DD/4; k4++) {
                float4 a = ra[k4];
                float4 b0 = rb0[k4];
                float4 b1 = rb1[k4];
                acc0 = __fmaf_rn(a.x, b0.x, acc0);
                acc0 = __fmaf_rn(a.y, b0.y, acc0);
                acc0 = __fmaf_rn(a.z, b0.z, acc0);
                acc0 = __fmaf_rn(a.w, b0.w, acc0);
                acc1 = __fmaf_rn(a.x, b1.x, acc1);
                acc1 = __fmaf_rn(a.y, b1.y, acc1);
                acc1 = __fmaf_rn(a.z, b1.z, acc1);
                acc1 = __fmaf_rn(a.w, b1.w, acc1);
            }
        }
        // broadcast both dot sets to all lanes
        float blk0[25], blk1[25];
        #pragma unroll
        for (int i = 0; i < 25; i++) {
            blk0[i] = __shfl_sync(0xffffffffu, acc0, i);
            blk1[i] = __shfl_sync(0xffffffffu, acc1, i);
        }
        // lanes 0/1 reduce candidates cA/cB in parallel
        if (lane < 2) {
            int c = lane ? cB : cA;
            bool has = lane ? hasB : hasA;
            if (has) {
                const float* blk = lane ? blk1 : blk0;
                int j = s_cand[c];
                int nsb = (int)g_ns[1-dir][j];
                float ls1s = 0.0f, c1 = 0.0f;
                #pragma unroll
                for (int nn = 0; nn < 5; nn++) {
                    float mx = -3.0e38f;
                    #pragma unroll
                    for (int mm = 0; mm < 5; mm++) {
                        float sv = (nn < nsa && mm < nsb) ? blk[nn*5 + mm] : -1.0f;
                        mx = fmaxf(mx, sv);
                    }
                    float v1 = (mx != -1.0f) ? 1.0f : 0.0f;
                    ls1s = fa(ls1s, fm(mx, v1)); c1 = fa(c1, v1);
                }
                float ls2s = 0.0f, c2 = 0.0f;
                #pragma unroll
                for (int mm = 0; mm < 5; mm++) {
                    float mx = -3.0e38f;
                    #pragma unroll
                    for (int nn = 0; nn < 5; nn++) {
                        float sv = (nn < nsa && mm < nsb) ? blk[nn*5 + mm] : -1.0f;
                        mx = fmaxf(mx, sv);
                    }
                    float v2 = (mx != -1.0f) ? 1.0f : 0.0f;
                    ls2s = fa(ls2s, fm(mx, v2)); c2 = fa(c2, v2);
                }
                s_cex[c] = __fdiv_rn(fa(__fdiv_rn(ls1s, c1), __fdiv_rn(ls2s, c2)), 2.0f);
            }
        }
        __syncthreads();
    }

    // Phase 4: exact top-10 among candidates (same argsort-key semantics)
    if (wid == 0) {
        unsigned long long prv = 0xFFFFFFFFFFFFFFFFull;
        for (int s = 0; s < TK; s++) {
            unsigned long long best = 0ull;
            for (int c = lane; c < ncand; c += 32) {
                unsigned long long key =
                    ((unsigned long long)enc_f(s_cex[c]) << 32) | (unsigned)s_cand[c];
                if (key < prv && key > best) best = key;
            }
            #pragma unroll
            for (int off = 16; off; off >>= 1) {
                unsigned long long o = __shfl_xor_sync(0xffffffffu, best, off);
                if (o > best) best = o;
            }
            prv = best;
            if (lane == 0) g_topk[dir][row*TK + (TK-1-s)] = (int)(best & 0xFFFFFFFFull);
        }
    }
}

// -------- kernel 4: NW (interleaved 2-cand chains) + fused argmax ------------
__global__ void nw_kernel() {
    __shared__ __align__(16) float sA[5][132];
    __shared__ __align__(16) float sB[10][5][132];
    __shared__ float s_blk[10][26];
    __shared__ int s_top[10];
    __shared__ float s_nw[2*TK];
    int line = blockIdx.x;
    int dir  = blockIdx.y;
    int t    = threadIdx.x;                 // 160

    const float* dA = dir ? g_d2 : g_d1;
    const float* dB = dir ? g_d1 : g_d2;

    if (t < 10) s_top[t] = g_topk[dir][line*TK + t];
    __syncthreads();

    {
        int r = t >> 5, c4 = t & 31;
        *(float4*)&sA[r][c4*4] = *(const float4*)&dA[(line*NS + r)*DD + c4*4];
    }
    #pragma unroll
    for (int i = 0; i < 10; i++) {
        int j = s_top[i];
        int r = t >> 5, c4 = t & 31;
        *(float4*)&sB[i][r][c4*4] = *(const float4*)&dB[(j*NS + r)*DD + c4*4];
    }
    __syncthreads();

    int warp = t >> 5, lane = t & 31;
    int na = (int)g_ns[dir][line];
    int n = lane / 5, m = lane - n*5;
    int c0 = warp*2, c1 = warp*2 + 1;

    float acc0 = 0.0f, acc1 = 0.0f;
    if (lane < 25) {
        const float4* ra  = (const float4*)&sA[n][0];
        const float4* rb0 = (const float4*)&sB[c0][m][0];
        const float4* rb1 = (const float4*)&sB[c1][m][0];
        #pragma unroll 8
        for (int k4 = 0; k4 < DD/4; k4++) {
            float4 a = ra[k4];
            float4 b0 = rb0[k4];
            float4 b1 = rb1[k4];
            acc0 = __fmaf_rn(a.x, b0.x, acc0);
            acc0 = __fmaf_rn(a.y, b0.y, acc0);
            acc0 = __fmaf_rn(a.z, b0.z, acc0);
            acc0 = __fmaf_rn(a.w, b0.w, acc0);
            acc1 = __fmaf_rn(a.x, b1.x, acc1);
            acc1 = __fmaf_rn(a.y, b1.y, acc1);
            acc1 = __fmaf_rn(a.z, b1.z, acc1);
            acc1 = __fmaf_rn(a.w, b1.w, acc1);
        }
        s_blk[c0][lane] = acc0;
        s_blk[c1][lane] = acc1;
    }
    __syncwarp();

    if (lane < 4) {
        int c    = (lane >> 1) ? c1 : c0;
        int flip = lane & 1;
        int j = s_top[c];
        int nb = (int)g_ns[1-dir][j];
        const float* blk = &s_blk[c][0];
        float prev[6] = {0,0,0,0,0,0};
        #pragma unroll
        for (int r = 0; r < 5; r++) {
            float cur[6]; cur[0] = 0.0f;
            #pragma unroll
            for (int cI = 0; cI < 5; cI++) {
                int sm = flip ? (4 - cI) : cI;
                float sv = (r < na && sm < nb) ? blk[r*5 + sm] : -1.0f;
                sv = fs(sv, GAPF);
                cur[cI+1] = fmaxf(fmaxf(cur[cI], prev[cI+1]), fa(prev[cI], sv));
            }
            #pragma unroll
            for (int cI = 0; cI < 6; cI++) prev[cI] = cur[cI];
        }
        g_nw[dir][line*2*TK + flip*TK + c] = prev[5];
        s_nw[flip*TK + c] = prev[5];
    }
    __syncthreads();

    if (t == 0) {
        float best = s_nw[0]; int bi = 0;
        for (int q = 1; q < 2*TK; q++)
            if (s_nw[q] > best) { best = s_nw[q]; bi = q; }
        g_match[dir][line] = s_top[bi % TK];
    }
}

// ---------------- kernel 5: mutual check + write output ----------------------
__global__ void final_kernel(float* __restrict__ out, int out_size) {
    int idx = blockIdx.x * blockDim.x + threadIdx.x;
    if (idx >= NL + NL*2*TK || idx >= out_size) return;
    if (idx < NL) {
        int m  = g_match[0][idx];
        int ok = (g_match[1][m] == idx);
        out[idx] = ok ? (float)m : -1.0f;
    } else {
        out[idx] = g_nw[0][idx - NL];
    }
}

// ---------------- launcher ---------------------------------------------------
extern "C" void kernel_launch(void* const* d_in, const int* in_sizes, int n_in,
                              void* d_out, int out_size) {
    const float* seg1  = (const float*)d_in[0];
    const float* seg2  = (const float*)d_in[1];
    const float* desc1 = (const float*)d_in[2];
    const float* desc2 = (const float*)d_in[3];

    static int smem_set = 0;
    if (!smem_set) {
        cudaFuncSetAttribute(ls_wmma_kernel,
                             cudaFuncAttributeMaxDynamicSharedMemorySize, SMEM_WMMA);
        smem_set = 1;
    }

    shift_kernel<<<1, 32>>>();   // shifts ncu -s window onto topk_rescue_kernel
    {
        int warps = 2*NPTS;
        int threads = warps*32;
        sample_kernel<<<(threads + 255)/256, 256>>>(seg1, seg2, desc1, desc2);
    }
    ls_wmma_kernel<<<dim3(NL/LPB, NL/LPB), 512, SMEM_WMMA>>>();
    topk_rescue_kernel<<<dim3(NL, 2), 256>>>();
    nw_kernel<<<dim3(NL, 2), 160>>>();
    final_kernel<<<(NL + NL*2*TK + 255)/256, 256>>>((float*)d_out, out_size);
}